// round 11
// baseline (speedup 1.0000x reference)
#include <cuda_runtime.h>
#include <cuda_bf16.h>
#include <math.h>
#include <stdint.h>

#define SQ   2048
#define HID  2048
#define MR   4096

typedef __nv_bfloat16  bf16;
typedef __nv_bfloat162 bf162;

// ----------------------------- static scratch ------------------------------
__device__ float g_qkv[3u * MR * HID];
__device__ float g_ao [MR * HID];
__device__ float g_bm [SQ];
__device__ float g_attn[134217728];

__device__ bf16 g_xh [MR * HID],  g_xl [MR * HID];
__device__ bf16 g_wh [3u * HID * HID], g_wl[3u * HID * HID];
__device__ bf16 g_woh[HID * HID], g_wol[HID * HID];
__device__ bf16 g_qh [MR * HID],  g_ql [MR * HID];
__device__ bf16 g_kh [MR * HID],  g_kl [MR * HID];
__device__ bf16 g_vth[MR * HID],  g_vtl[MR * HID];
__device__ bf16 g_aoh[MR * HID],  g_aol[MR * HID];
__device__ bf16 g_ah [134217728], g_al [134217728];

// ----------------------------- helpers -------------------------------------
__device__ __forceinline__ uint32_t smem_u32(const void* p) {
    uint32_t a;
    asm("{ .reg .u64 t; cvta.to.shared.u64 t, %1; cvt.u32.u64 %0, t; }" : "=r"(a) : "l"(p));
    return a;
}
__device__ __forceinline__ void cp16(uint32_t dst, const void* src) {
    asm volatile("cp.async.cg.shared.global [%0], [%1], 16;" :: "r"(dst), "l"(src));
}
#define CP_COMMIT() asm volatile("cp.async.commit_group;" ::: "memory")
#define CP_WAIT(n)  asm volatile("cp.async.wait_group %0;" :: "n"(n) : "memory")

#define LDSM4(r0, r1, r2, r3, addr) \
    asm volatile("ldmatrix.sync.aligned.m8n8.x4.shared.b16 {%0,%1,%2,%3}, [%4];" \
        : "=r"(r0), "=r"(r1), "=r"(r2), "=r"(r3) : "r"(addr))

__device__ __forceinline__ void mma_bf16(float* c,
    uint32_t a0, uint32_t a1, uint32_t a2, uint32_t a3, uint32_t b0, uint32_t b1)
{
    asm volatile(
        "mma.sync.aligned.m16n8k16.row.col.f32.bf16.bf16.f32 "
        "{%0,%1,%2,%3}, {%4,%5,%6,%7}, {%8,%9}, {%0,%1,%2,%3};"
        : "+f"(c[0]), "+f"(c[1]), "+f"(c[2]), "+f"(c[3])
        : "r"(a0), "r"(a1), "r"(a2), "r"(a3), "r"(b0), "r"(b1));
}

// =================================================================================
// Split-bf16 NT GEMM via mma.sync. CTA 128x128, 8 warps (2x4) of 64x32.
// BK=64 stages (half the waits/barriers of BK=32), double-buffered cp.async.
// Smem/stage: Ah,Al,Bh,Bl each 128x72 bf16 (pad 8) = 18432 B -> 73728 B; x2 stages.
// mode&1: causal tile skip. mode&2: Keff = rowBase+128 (causal attn@v).
// =================================================================================
#define ARR_BYTES 18432u           // 128*72*2
#define STG_BYTES 73728u           // 4*ARR_BYTES

__device__ __forceinline__ void load_stage64(
    uint32_t sbase, int slot, int k0,
    const bf16* __restrict__ Ah, const bf16* __restrict__ Al,
    const bf16* __restrict__ Bh, const bf16* __restrict__ Bl,
    int lda, int ldb, int rowBase, int colBase, int tid)
{
    uint32_t base = sbase + (uint32_t)slot * STG_BYTES;
    int r  = tid >> 1;              // 0..127
    int c0 = (tid & 1) << 2;        // 0 or 4
#pragma unroll
    for (int i = 0; i < 4; i++) {
        int c = c0 + i;             // 8-bf16 chunk 0..7
        uint32_t off = (uint32_t)(r * 72 + c * 8) * 2;
        const size_t ga = (size_t)(rowBase + r) * lda + k0 + c * 8;
        const size_t gb = (size_t)(colBase + r) * ldb + k0 + c * 8;
        cp16(base +                off, Ah + ga);
        cp16(base + ARR_BYTES    + off, Al + ga);
        cp16(base + 2u*ARR_BYTES + off, Bh + gb);
        cp16(base + 3u*ARR_BYTES + off, Bl + gb);
    }
    CP_COMMIT();
}

__global__ void __launch_bounds__(256, 1)
mma_gemm(const bf16* __restrict__ Ahi, const bf16* __restrict__ Alo,
         const bf16* __restrict__ Bhi, const bf16* __restrict__ Blo,
         float* __restrict__ C,
         int K, int lda, int ldb, int ldc,
         long long aSb, long long aSh, long long bSb, long long bSh,
         long long cSb, long long cSh, int nInner, float scale, int mode)
{
    extern __shared__ char smem[];
    const int z  = blockIdx.z;
    const int bb = z / nInner, hh = z - bb * nInner;
    const bf16* Ah = Ahi + bb * aSb + hh * aSh;
    const bf16* Al = Alo + bb * aSb + hh * aSh;
    const bf16* Bh = Bhi + bb * bSb + hh * bSh;
    const bf16* Bl = Blo + bb * bSb + hh * bSh;
    float* Cz = C + bb * cSb + hh * cSh;

    const int rowBase = blockIdx.y * 128;
    const int colBase = blockIdx.x * 128;
    if ((mode & 1) && colBase > rowBase + 127) return;
    int Keff = K;
    if (mode & 2) { int kl = rowBase + 128; Keff = kl < K ? kl : K; }
    const int nst = Keff >> 6;      // 64-K stages

    const uint32_t sb = smem_u32(smem);
    const int tid = threadIdx.x, lane = tid & 31, wid = tid >> 5;
    const int warpM = (wid & 1) << 6;
    const int warpN = (wid >> 1) << 5;

    const uint32_t offA = (uint32_t)((warpM + (lane & 15)) * 72
                                     + ((lane >> 4) << 3)) * 2;
    const uint32_t offB = (uint32_t)((warpN + (lane & 7) + ((lane >> 4) << 3)) * 72
                                     + (((lane >> 3) & 1) << 3)) * 2;

    float acc[4][4][4];
#pragma unroll
    for (int i = 0; i < 4; i++)
#pragma unroll
        for (int j = 0; j < 4; j++)
#pragma unroll
            for (int t = 0; t < 4; t++) acc[i][j][t] = 0.f;

    load_stage64(sb, 0, 0, Ah, Al, Bh, Bl, lda, ldb, rowBase, colBase, tid);

    for (int j = 0; j < nst; j++) {
        if (j + 1 < nst) {
            load_stage64(sb, (j + 1) & 1, (j + 1) * 64, Ah, Al, Bh, Bl,
                         lda, ldb, rowBase, colBase, tid);
            CP_WAIT(1);
        } else {
            CP_WAIT(0);
        }
        __syncthreads();

        const uint32_t base = sb + (uint32_t)(j & 1) * STG_BYTES;
#pragma unroll
        for (int ks = 0; ks < 64; ks += 16) {
            uint32_t ah[4][4], al[4][4], bh[2][4], bl[2][4];
#pragma unroll
            for (int t = 0; t < 4; t++) {
                uint32_t ad = base + offA + (uint32_t)((t * 1152 + ks) * 2);
                LDSM4(ah[t][0], ah[t][1], ah[t][2], ah[t][3], ad);
                LDSM4(al[t][0], al[t][1], al[t][2], al[t][3], ad + ARR_BYTES);
            }
#pragma unroll
            for (int g = 0; g < 2; g++) {
                uint32_t bd = base + 2u*ARR_BYTES + offB + (uint32_t)((g * 1152 + ks) * 2);
                LDSM4(bh[g][0], bh[g][1], bh[g][2], bh[g][3], bd);
                LDSM4(bl[g][0], bl[g][1], bl[g][2], bl[g][3], bd + ARR_BYTES);
            }
#pragma unroll
            for (int mt = 0; mt < 4; mt++) {
#pragma unroll
                for (int g = 0; g < 2; g++) {
                    mma_bf16(acc[mt][2*g],   ah[mt][0], ah[mt][1], ah[mt][2], ah[mt][3], bh[g][0], bh[g][1]);
                    mma_bf16(acc[mt][2*g+1], ah[mt][0], ah[mt][1], ah[mt][2], ah[mt][3], bh[g][2], bh[g][3]);
                    mma_bf16(acc[mt][2*g],   ah[mt][0], ah[mt][1], ah[mt][2], ah[mt][3], bl[g][0], bl[g][1]);
                    mma_bf16(acc[mt][2*g+1], ah[mt][0], ah[mt][1], ah[mt][2], ah[mt][3], bl[g][2], bl[g][3]);
                    mma_bf16(acc[mt][2*g],   al[mt][0], al[mt][1], al[mt][2], al[mt][3], bh[g][0], bh[g][1]);
                    mma_bf16(acc[mt][2*g+1], al[mt][0], al[mt][1], al[mt][2], al[mt][3], bh[g][2], bh[g][3]);
                }
            }
        }
        __syncthreads();
    }

    const int row0 = rowBase + warpM + (lane >> 2);
    const int col0 = colBase + warpN + (lane & 3) * 2;
#pragma unroll
    for (int mt = 0; mt < 4; mt++) {
#pragma unroll
        for (int nt = 0; nt < 4; nt++) {
            float2 v0 = make_float2(acc[mt][nt][0] * scale, acc[mt][nt][1] * scale);
            float2 v1 = make_float2(acc[mt][nt][2] * scale, acc[mt][nt][3] * scale);
            size_t r0 = (size_t)(row0 + mt * 16) * ldc + col0 + nt * 8;
            *reinterpret_cast<float2*>(Cz + r0)                   = v0;
            *reinterpret_cast<float2*>(Cz + r0 + 8 * (size_t)ldc) = v1;
        }
    }
}

// =================================================================================
// Elementwise kernels
// =================================================================================
__device__ __forceinline__ void sp(float v, bf16& h, bf16& l) {
    h = __float2bfloat16_rn(v);
    l = __float2bfloat16_rn(v - __bfloat162float(h));
}

__global__ void split_kernel(const float* __restrict__ in,
                             bf16* __restrict__ hi, bf16* __restrict__ lo, int n4)
{
    int i = blockIdx.x * 256 + threadIdx.x;
    if (i >= n4) return;
    float4 v = reinterpret_cast<const float4*>(in)[i];
    bf16 h0, l0, h1, l1, h2, l2, h3, l3;
    sp(v.x, h0, l0); sp(v.y, h1, l1); sp(v.z, h2, l2); sp(v.w, h3, l3);
    bf162 a, b;
    a.x = h0; a.y = h1; b.x = h2; b.y = h3;
    reinterpret_cast<bf162*>(hi)[i * 2] = a; reinterpret_cast<bf162*>(hi)[i * 2 + 1] = b;
    a.x = l0; a.y = l1; b.x = l2; b.y = l3;
    reinterpret_cast<bf162*>(lo)[i * 2] = a; reinterpret_cast<bf162*>(lo)[i * 2 + 1] = b;
}

__global__ void bmean_kernel(const float* __restrict__ bias, float* __restrict__ bm)
{
    __shared__ float red[256];
    int r = blockIdx.x;
    const float* row = bias + (size_t)r * SQ;
    float s = 0.f;
    for (int i = threadIdx.x; i < SQ; i += 256) s += row[i];
    red[threadIdx.x] = s; __syncthreads();
    for (int o = 128; o; o >>= 1) {
        if (threadIdx.x < o) red[threadIdx.x] += red[threadIdx.x + o];
        __syncthreads();
    }
    if (threadIdx.x == 0) bm[r] = red[0] * (0.1f / 2048.0f);
}

__global__ void rope_split_kernel(const float* __restrict__ q, const float* __restrict__ k,
                                  const float* __restrict__ bm,
                                  bf16* __restrict__ qh, bf16* __restrict__ ql,
                                  bf16* __restrict__ kh, bf16* __restrict__ kl)
{
    __shared__ float sinvf[64];
    if (threadIdx.x < 64)
        sinvf[threadIdx.x] =
            (float)exp(-((double)(2 * threadIdx.x) / 128.0) * log(10000.0));
    __syncthreads();

    int idx = blockIdx.x * 256 + threadIdx.x;
    int d2 = idx & 63;
    int h  = (idx >> 6) & 15;
    int m  = idx >> 10;
    int s  = m & (SQ - 1);

    float sn, cs;
    sincosf((float)s * sinvf[d2], &sn, &cs);
    float b = bm[s];

    size_t off = (size_t)m * HID + (size_t)h * 128 + d2;
    float q0 = q[off], q1 = q[off + 64];
    float k0 = k[off], k1 = k[off + 64];
    float qa = q0 * cs - q1 * sn + b;
    float qb = q1 * cs + q0 * sn + b;
    float ka = k0 * cs - k1 * sn + b;
    float kb = k1 * cs + k0 * sn + b;
    bf16 h_, l_;
    sp(qa, h_, l_); qh[off]      = h_; ql[off]      = l_;
    sp(qb, h_, l_); qh[off + 64] = h_; ql[off + 64] = l_;
    sp(ka, h_, l_); kh[off]      = h_; kl[off]      = l_;
    sp(kb, h_, l_); kh[off + 64] = h_; kl[off + 64] = l_;
}

__global__ void vsplit_kernel(const float* __restrict__ v,
                              bf16* __restrict__ vth, bf16* __restrict__ vtl)
{
    __shared__ float t[32][33];
    int z = blockIdx.z, b = z >> 4, h = z & 15;
    int s0 = blockIdx.x * 32, d0 = blockIdx.y * 32;
    int tx = threadIdx.x, ty = threadIdx.y;
#pragma unroll
    for (int i = 0; i < 4; i++) {
        int sl = ty * 4 + i;
        t[sl][tx] = v[(size_t)(b * SQ + s0 + sl) * HID + h * 128 + d0 + tx];
    }
    __syncthreads();
#pragma unroll
    for (int i = 0; i < 4; i++) {
        int dl = ty * 4 + i;
        float x = t[tx][dl];
        bf16 hi, lo; sp(x, hi, lo);
        size_t o = ((size_t)z * 128 + d0 + dl) * SQ + s0 + tx;
        vth[o] = hi; vtl[o] = lo;
    }
}

__global__ void softmax_kernel(float* __restrict__ attn, const float* __restrict__ bias,
                               bf16* __restrict__ ah, bf16* __restrict__ al,
                               int writeAttn)
{
    __shared__ float buf[2048];
    __shared__ float red[256];
    int qrow = blockIdx.x;
    long long base = (long long)blockIdx.y * SQ * SQ + (long long)qrow * SQ;
    float* row = attn + base;
    const float* brow = bias + (size_t)qrow * SQ;
    int L  = qrow + 1;
    int L4 = L & ~3;
    int tileEnd = ((qrow >> 7) + 1) << 7;
    int tid = threadIdx.x;

    float mx = -3.402823466e38f;
    for (int i = tid * 4; i < L4; i += 1024) {
        float4 r = *reinterpret_cast<const float4*>(row + i);
        float4 bb = *reinterpret_cast<const float4*>(brow + i);
        r.x += bb.x; r.y += bb.y; r.z += bb.z; r.w += bb.w;
        *reinterpret_cast<float4*>(buf + i) = r;
        mx = fmaxf(mx, fmaxf(fmaxf(r.x, r.y), fmaxf(r.z, r.w)));
    }
    for (int i = L4 + tid; i < L; i += 256) {
        float vv = row[i] + brow[i];
        buf[i] = vv;
        mx = fmaxf(mx, vv);
    }
    red[tid] = mx; __syncthreads();
    for (int o = 128; o; o >>= 1) {
        if (tid < o) red[tid] = fmaxf(red[tid], red[tid + o]);
        __syncthreads();
    }
    mx = red[0]; __syncthreads();

    float sum = 0.f;
    for (int i = tid; i < L; i += 256) {
        float e = __expf(buf[i] - mx);
        buf[i] = e;
        sum += e;
    }
    red[tid] = sum; __syncthreads();
    for (int o = 128; o; o >>= 1) {
        if (tid < o) red[tid] += red[tid + o];
        __syncthreads();
    }
    float inv = 1.0f / red[0];
    __syncthreads();

    for (int i = tid * 4; i < L4; i += 1024) {
        float a0 = buf[i]     * inv;
        float a1 = buf[i + 1] * inv;
        float a2 = buf[i + 2] * inv;
        float a3 = buf[i + 3] * inv;
        bf16 h0, l0, h1, l1, h2, l2, h3, l3;
        sp(a0, h0, l0); sp(a1, h1, l1); sp(a2, h2, l2); sp(a3, h3, l3);
        bf162 p; p.x = h0; p.y = h1;
        *reinterpret_cast<bf162*>(ah + base + i)     = p;
        p.x = h2; p.y = h3;
        *reinterpret_cast<bf162*>(ah + base + i + 2) = p;
        p.x = l0; p.y = l1;
        *reinterpret_cast<bf162*>(al + base + i)     = p;
        p.x = l2; p.y = l3;
        *reinterpret_cast<bf162*>(al + base + i + 2) = p;
        if (writeAttn)
            *reinterpret_cast<float4*>(row + i) = make_float4(a0, a1, a2, a3);
    }
    for (int i = L4 + tid; i < L; i += 256) {
        float a = buf[i] * inv;
        bf16 hi, lo; sp(a, hi, lo);
        ah[base + i] = hi; al[base + i] = lo;
        if (writeAttn) row[i] = a;
    }
    bf16 z16 = __float2bfloat16_rn(0.f);
    for (int i = L + tid; i < tileEnd; i += 256) { ah[base + i] = z16; al[base + i] = z16; }
    if (writeAttn)
        for (int i = L + tid; i < SQ; i += 256) row[i] = 0.f;
}

// =================================================================================
// Host launcher — launch order arranged so launch #6 is the QKV mma_gemm
// (ncu capture is -s 5 -c 1), so we finally profile the GEMM.
// =================================================================================
extern "C" void kernel_launch(void* const* d_in, const int* in_sizes, int n_in,
                              void* d_out, int out_size)
{
    const float* x    = (const float*)d_in[0];
    const float* Wq   = (const float*)d_in[1];
    const float* Wk   = (const float*)d_in[2];
    const float* Wv   = (const float*)d_in[3];
    const float* Wo   = (const float*)d_in[4];
    const float* bias = (const float*)d_in[5];
    float* out = (float*)d_out;

    float *pqkv, *pao, *pbm, *pattn;
    bf16 *pxh, *pxl, *pwh, *pwl, *pwoh, *pwol;
    bf16 *pqh, *pql, *pkh, *pkl, *pvth, *pvtl, *paoh, *paol, *pah, *pal;
    cudaGetSymbolAddress((void**)&pqkv, g_qkv); cudaGetSymbolAddress((void**)&pao, g_ao);
    cudaGetSymbolAddress((void**)&pbm, g_bm);   cudaGetSymbolAddress((void**)&pattn, g_attn);
    cudaGetSymbolAddress((void**)&pxh, g_xh);   cudaGetSymbolAddress((void**)&pxl, g_xl);
    cudaGetSymbolAddress((void**)&pwh, g_wh);   cudaGetSymbolAddress((void**)&pwl, g_wl);
    cudaGetSymbolAddress((void**)&pwoh, g_woh); cudaGetSymbolAddress((void**)&pwol, g_wol);
    cudaGetSymbolAddress((void**)&pqh, g_qh);   cudaGetSymbolAddress((void**)&pql, g_ql);
    cudaGetSymbolAddress((void**)&pkh, g_kh);   cudaGetSymbolAddress((void**)&pkl, g_kl);
    cudaGetSymbolAddress((void**)&pvth, g_vth); cudaGetSymbolAddress((void**)&pvtl, g_vtl);
    cudaGetSymbolAddress((void**)&paoh, g_aoh); cudaGetSymbolAddress((void**)&paol, g_aol);
    cudaGetSymbolAddress((void**)&pah, g_ah);   cudaGetSymbolAddress((void**)&pal, g_al);

    const long long OUT_N = 8388608LL, ATT_N = 134217728LL;
    float* outPtr = out;
    float* attnPtr;
    int writeAttn = 1;
    long long osz = (long long)out_size;
    if (osz >= OUT_N + ATT_N) { attnPtr = out + OUT_N; }
    else if (osz == ATT_N)    { attnPtr = out; outPtr = pqkv; }
    else                      { attnPtr = pattn; writeAttn = 0; }

    const long long SH = (long long)SQ * HID;
    const long long SS = (long long)SQ * SQ;
    const long long WW = (long long)HID * HID;
    const long long QKVS = (long long)MR * HID;
    const int SMEM = 2 * 73728;    // 147456 B
    cudaFuncSetAttribute(mma_gemm, cudaFuncAttributeMaxDynamicSharedMemorySize, SMEM);

    // launches 1..5: splits
    split_kernel<<<8192, 256>>>(x,  pxh, pxl, 2097152);
    split_kernel<<<4096, 256>>>(Wq, pwh,        pwl,        1048576);
    split_kernel<<<4096, 256>>>(Wk, pwh + WW,   pwl + WW,   1048576);
    split_kernel<<<4096, 256>>>(Wv, pwh + 2*WW, pwl + 2*WW, 1048576);
    split_kernel<<<4096, 256>>>(Wo, pwoh, pwol, 1048576);

    // launch 6: merged QKV projection (this is what ncu -s 5 -c 1 captures)
    dim3 gQKV(16, 32, 3);
    mma_gemm<<<gQKV, 256, SMEM>>>(pxh, pxl, pwh, pwl, pqkv, 2048, 2048, 2048, 2048,
                                  0, 0, WW, 0, QKVS, 0, 1, 1.0f, 0);

    bmean_kernel<<<SQ, 256>>>(bias, pbm);

    float* pq = pqkv;
    float* pk = pqkv + QKVS;
    float* pv = pqkv + 2 * QKVS;
    rope_split_kernel<<<16384, 256>>>(pq, pk, pbm, pqh, pql, pkh, pkl);
    vsplit_kernel<<<dim3(64, 4, 32), dim3(32, 8)>>>(pv, pvth, pvtl);

    // scores = q.k^T / sqrt(128), causal tile-skip
    dim3 gScore(16, 16, 32);
    mma_gemm<<<gScore, 256, SMEM>>>(pqh, pql, pkh, pkl, attnPtr, 128, 2048, 2048, 2048,
                                    SH, 128, SH, 128,
                                    16 * SS, SS, 16, 0.08838834764831845f, 1);

    softmax_kernel<<<dim3(SQ, 32), 256>>>(attnPtr, bias, pah, pal, writeAttn);

    // attn @ v, K-limited by causality
    dim3 gAV(1, 16, 32);
    mma_gemm<<<gAV, 256, SMEM>>>(pah, pal, pvth, pvtl, pao, 2048, 2048, 2048, 2048,
                                 16 * SS, SS, SH, (long long)128 * SQ,
                                 SH, 128, 16, 1.0f, 2);

    split_kernel<<<8192, 256>>>(pao, paoh, paol, 2097152);

    // output = attn_out @ Wo^T
    dim3 gProj(16, 32, 1);
    mma_gemm<<<gProj, 256, SMEM>>>(paoh, paol, pwoh, pwol, outPtr, 2048, 2048, 2048, 2048,
                                   0, 0, 0, 0, 0, 0, 1, 1.0f, 0);
}

// round 12
// speedup vs baseline: 1.0515x; 1.0515x over previous
#include <cuda_runtime.h>
#include <cuda_bf16.h>
#include <math.h>
#include <stdint.h>

#define SQ   2048
#define HID  2048
#define MR   4096

typedef __nv_bfloat16  bf16;
typedef __nv_bfloat162 bf162;

// ----------------------------- static scratch ------------------------------
__device__ float g_qkv[3u * MR * HID];
__device__ float g_ao [MR * HID];
__device__ float g_bm [SQ];
__device__ float g_attn[134217728];

__device__ bf16 g_xh [MR * HID],  g_xl [MR * HID];
__device__ bf16 g_wh [3u * HID * HID], g_wl[3u * HID * HID];
__device__ bf16 g_woh[HID * HID], g_wol[HID * HID];
__device__ bf16 g_qh [MR * HID],  g_ql [MR * HID];
__device__ bf16 g_kh [MR * HID],  g_kl [MR * HID];
__device__ bf16 g_vth[MR * HID],  g_vtl[MR * HID];
__device__ bf16 g_aoh[MR * HID],  g_aol[MR * HID];
__device__ bf16 g_ah [134217728], g_al [134217728];

// ----------------------------- helpers -------------------------------------
__device__ __forceinline__ uint32_t smem_u32(const void* p) {
    uint32_t a;
    asm("{ .reg .u64 t; cvta.to.shared.u64 t, %1; cvt.u32.u64 %0, t; }" : "=r"(a) : "l"(p));
    return a;
}
__device__ __forceinline__ void cp16(uint32_t dst, const void* src) {
    asm volatile("cp.async.cg.shared.global [%0], [%1], 16;" :: "r"(dst), "l"(src));
}
#define CP_COMMIT() asm volatile("cp.async.commit_group;" ::: "memory")
#define CP_WAIT(n)  asm volatile("cp.async.wait_group %0;" :: "n"(n) : "memory")

#define LDSM4(r0, r1, r2, r3, addr) \
    asm volatile("ldmatrix.sync.aligned.m8n8.x4.shared.b16 {%0,%1,%2,%3}, [%4];" \
        : "=r"(r0), "=r"(r1), "=r"(r2), "=r"(r3) : "r"(addr))

__device__ __forceinline__ void mma_bf16(float* c,
    uint32_t a0, uint32_t a1, uint32_t a2, uint32_t a3, uint32_t b0, uint32_t b1)
{
    asm volatile(
        "mma.sync.aligned.m16n8k16.row.col.f32.bf16.bf16.f32 "
        "{%0,%1,%2,%3}, {%4,%5,%6,%7}, {%8,%9}, {%0,%1,%2,%3};"
        : "+f"(c[0]), "+f"(c[1]), "+f"(c[2]), "+f"(c[3])
        : "r"(a0), "r"(a1), "r"(a2), "r"(a3), "r"(b0), "r"(b1));
}

// =================================================================================
// Split-bf16 NT GEMM via mma.sync. CTA 128x128, 8 warps (2x4) of 64x32, BK=32.
// 3-slot cp.async ring (prefetch distance 2). Smem 3*40960 = 120 KB, 1 CTA/SM.
// mode&1: causal tile skip. mode&2: Keff = rowBase+128 (causal attn@v).
// mode&4: reverse y->rowBase mapping (heavy-first scheduling for attn@v).
// =================================================================================
#define STG_BYTES 40960u
#define ARR_BYTES 10240u   // 128*40*2

__device__ __forceinline__ void load_stage32(
    uint32_t sbase, int slot, int k0,
    const bf16* __restrict__ Ah, const bf16* __restrict__ Al,
    const bf16* __restrict__ Bh, const bf16* __restrict__ Bl,
    int lda, int ldb, int rowBase, int colBase, int tid)
{
    uint32_t base = sbase + (uint32_t)slot * STG_BYTES;
    int r  = tid >> 1;
    int c0 = (tid & 1) << 1;
#pragma unroll
    for (int i = 0; i < 2; i++) {
        int c = c0 + i;
        uint32_t off = (uint32_t)(r * 40 + c * 8) * 2;
        const size_t ga = (size_t)(rowBase + r) * lda + k0 + c * 8;
        const size_t gb = (size_t)(colBase + r) * ldb + k0 + c * 8;
        cp16(base +                off, Ah + ga);
        cp16(base + ARR_BYTES    + off, Al + ga);
        cp16(base + 2u*ARR_BYTES + off, Bh + gb);
        cp16(base + 3u*ARR_BYTES + off, Bl + gb);
    }
    CP_COMMIT();
}

__global__ void __launch_bounds__(256, 1)
mma_gemm(const bf16* __restrict__ Ahi, const bf16* __restrict__ Alo,
         const bf16* __restrict__ Bhi, const bf16* __restrict__ Blo,
         float* __restrict__ C,
         int K, int lda, int ldb, int ldc,
         long long aSb, long long aSh, long long bSb, long long bSh,
         long long cSb, long long cSh, int nInner, float scale, int mode)
{
    extern __shared__ char smem[];
    const int z  = blockIdx.z;
    const int bb = z / nInner, hh = z - bb * nInner;
    const bf16* Ah = Ahi + bb * aSb + hh * aSh;
    const bf16* Al = Alo + bb * aSb + hh * aSh;
    const bf16* Bh = Bhi + bb * bSb + hh * bSh;
    const bf16* Bl = Blo + bb * bSb + hh * bSh;
    float* Cz = C + bb * cSb + hh * cSh;

    const int yIdx = (mode & 4) ? (gridDim.y - 1 - blockIdx.y) : blockIdx.y;
    const int rowBase = yIdx * 128;
    const int colBase = blockIdx.x * 128;
    if ((mode & 1) && colBase > rowBase + 127) return;
    int Keff = K;
    if (mode & 2) { int kl = rowBase + 128; Keff = kl < K ? kl : K; }
    const int nst = Keff >> 5;

    const uint32_t sb = smem_u32(smem);
    const int tid = threadIdx.x, lane = tid & 31, wid = tid >> 5;
    const int warpM = (wid & 1) << 6;
    const int warpN = (wid >> 1) << 5;

    const uint32_t offA = (uint32_t)((warpM + (lane & 15)) * 40
                                     + ((lane >> 4) << 3)) * 2;
    const uint32_t offB = (uint32_t)((warpN + (lane & 7) + ((lane >> 4) << 3)) * 40
                                     + (((lane >> 3) & 1) << 3)) * 2;

    float acc[4][4][4];
#pragma unroll
    for (int i = 0; i < 4; i++)
#pragma unroll
        for (int j = 0; j < 4; j++)
#pragma unroll
            for (int t = 0; t < 4; t++) acc[i][j][t] = 0.f;

    // 3-slot ring: prefetch stages 0 and 1
    load_stage32(sb, 0, 0, Ah, Al, Bh, Bl, lda, ldb, rowBase, colBase, tid);
    if (nst > 1)
        load_stage32(sb, 1, 32, Ah, Al, Bh, Bl, lda, ldb, rowBase, colBase, tid);

    int slot = 0;
    for (int j = 0; j < nst; j++) {
        if (j + 2 < nst) {
            int ns = slot + 2; if (ns >= 3) ns -= 3;
            load_stage32(sb, ns, (j + 2) * 32, Ah, Al, Bh, Bl,
                         lda, ldb, rowBase, colBase, tid);
            CP_WAIT(2);
        } else if (j + 1 < nst) {
            CP_WAIT(1);
        } else {
            CP_WAIT(0);
        }
        __syncthreads();

        const uint32_t base = sb + (uint32_t)slot * STG_BYTES;
#pragma unroll
        for (int ks = 0; ks < 32; ks += 16) {
            uint32_t ah[4][4], al[4][4], bh[2][4], bl[2][4];
#pragma unroll
            for (int t = 0; t < 4; t++) {
                uint32_t ad = base + offA + (uint32_t)((t * 640 + ks) * 2);
                LDSM4(ah[t][0], ah[t][1], ah[t][2], ah[t][3], ad);
                LDSM4(al[t][0], al[t][1], al[t][2], al[t][3], ad + ARR_BYTES);
            }
#pragma unroll
            for (int g = 0; g < 2; g++) {
                uint32_t bd = base + 2u*ARR_BYTES + offB + (uint32_t)((g * 640 + ks) * 2);
                LDSM4(bh[g][0], bh[g][1], bh[g][2], bh[g][3], bd);
                LDSM4(bl[g][0], bl[g][1], bl[g][2], bl[g][3], bd + ARR_BYTES);
            }
#pragma unroll
            for (int mt = 0; mt < 4; mt++) {
#pragma unroll
                for (int g = 0; g < 2; g++) {
                    mma_bf16(acc[mt][2*g],   ah[mt][0], ah[mt][1], ah[mt][2], ah[mt][3], bh[g][0], bh[g][1]);
                    mma_bf16(acc[mt][2*g+1], ah[mt][0], ah[mt][1], ah[mt][2], ah[mt][3], bh[g][2], bh[g][3]);
                    mma_bf16(acc[mt][2*g],   ah[mt][0], ah[mt][1], ah[mt][2], ah[mt][3], bl[g][0], bl[g][1]);
                    mma_bf16(acc[mt][2*g+1], ah[mt][0], ah[mt][1], ah[mt][2], ah[mt][3], bl[g][2], bl[g][3]);
                    mma_bf16(acc[mt][2*g],   al[mt][0], al[mt][1], al[mt][2], al[mt][3], bh[g][0], bh[g][1]);
                    mma_bf16(acc[mt][2*g+1], al[mt][0], al[mt][1], al[mt][2], al[mt][3], bh[g][2], bh[g][3]);
                }
            }
        }
        __syncthreads();
        if (++slot >= 3) slot = 0;
    }

    const int row0 = rowBase + warpM + (lane >> 2);
    const int col0 = colBase + warpN + (lane & 3) * 2;
#pragma unroll
    for (int mt = 0; mt < 4; mt++) {
#pragma unroll
        for (int nt = 0; nt < 4; nt++) {
            float2 v0 = make_float2(acc[mt][nt][0] * scale, acc[mt][nt][1] * scale);
            float2 v1 = make_float2(acc[mt][nt][2] * scale, acc[mt][nt][3] * scale);
            size_t r0 = (size_t)(row0 + mt * 16) * ldc + col0 + nt * 8;
            *reinterpret_cast<float2*>(Cz + r0)                   = v0;
            *reinterpret_cast<float2*>(Cz + r0 + 8 * (size_t)ldc) = v1;
        }
    }
}

// =================================================================================
// Elementwise kernels
// =================================================================================
__device__ __forceinline__ void sp(float v, bf16& h, bf16& l) {
    h = __float2bfloat16_rn(v);
    l = __float2bfloat16_rn(v - __bfloat162float(h));
}

__global__ void split_kernel(const float* __restrict__ in,
                             bf16* __restrict__ hi, bf16* __restrict__ lo, int n4)
{
    int i = blockIdx.x * 256 + threadIdx.x;
    if (i >= n4) return;
    float4 v = reinterpret_cast<const float4*>(in)[i];
    bf16 h0, l0, h1, l1, h2, l2, h3, l3;
    sp(v.x, h0, l0); sp(v.y, h1, l1); sp(v.z, h2, l2); sp(v.w, h3, l3);
    bf162 a, b;
    a.x = h0; a.y = h1; b.x = h2; b.y = h3;
    reinterpret_cast<bf162*>(hi)[i * 2] = a; reinterpret_cast<bf162*>(hi)[i * 2 + 1] = b;
    a.x = l0; a.y = l1; b.x = l2; b.y = l3;
    reinterpret_cast<bf162*>(lo)[i * 2] = a; reinterpret_cast<bf162*>(lo)[i * 2 + 1] = b;
}

__global__ void bmean_kernel(const float* __restrict__ bias, float* __restrict__ bm)
{
    __shared__ float red[256];
    int r = blockIdx.x;
    const float* row = bias + (size_t)r * SQ;
    float s = 0.f;
    for (int i = threadIdx.x; i < SQ; i += 256) s += row[i];
    red[threadIdx.x] = s; __syncthreads();
    for (int o = 128; o; o >>= 1) {
        if (threadIdx.x < o) red[threadIdx.x] += red[threadIdx.x + o];
        __syncthreads();
    }
    if (threadIdx.x == 0) bm[r] = red[0] * (0.1f / 2048.0f);
}

__global__ void rope_split_kernel(const float* __restrict__ q, const float* __restrict__ k,
                                  const float* __restrict__ bm,
                                  bf16* __restrict__ qh, bf16* __restrict__ ql,
                                  bf16* __restrict__ kh, bf16* __restrict__ kl)
{
    __shared__ float sinvf[64];
    if (threadIdx.x < 64)
        sinvf[threadIdx.x] =
            (float)exp(-((double)(2 * threadIdx.x) / 128.0) * log(10000.0));
    __syncthreads();

    int idx = blockIdx.x * 256 + threadIdx.x;
    int d2 = idx & 63;
    int h  = (idx >> 6) & 15;
    int m  = idx >> 10;
    int s  = m & (SQ - 1);

    float sn, cs;
    sincosf((float)s * sinvf[d2], &sn, &cs);
    float b = bm[s];

    size_t off = (size_t)m * HID + (size_t)h * 128 + d2;
    float q0 = q[off], q1 = q[off + 64];
    float k0 = k[off], k1 = k[off + 64];
    float qa = q0 * cs - q1 * sn + b;
    float qb = q1 * cs + q0 * sn + b;
    float ka = k0 * cs - k1 * sn + b;
    float kb = k1 * cs + k0 * sn + b;
    bf16 h_, l_;
    sp(qa, h_, l_); qh[off]      = h_; ql[off]      = l_;
    sp(qb, h_, l_); qh[off + 64] = h_; ql[off + 64] = l_;
    sp(ka, h_, l_); kh[off]      = h_; kl[off]      = l_;
    sp(kb, h_, l_); kh[off + 64] = h_; kl[off + 64] = l_;
}

__global__ void vsplit_kernel(const float* __restrict__ v,
                              bf16* __restrict__ vth, bf16* __restrict__ vtl)
{
    __shared__ float t[32][33];
    int z = blockIdx.z, b = z >> 4, h = z & 15;
    int s0 = blockIdx.x * 32, d0 = blockIdx.y * 32;
    int tx = threadIdx.x, ty = threadIdx.y;
#pragma unroll
    for (int i = 0; i < 4; i++) {
        int sl = ty * 4 + i;
        t[sl][tx] = v[(size_t)(b * SQ + s0 + sl) * HID + h * 128 + d0 + tx];
    }
    __syncthreads();
#pragma unroll
    for (int i = 0; i < 4; i++) {
        int dl = ty * 4 + i;
        float x = t[tx][dl];
        bf16 hi, lo; sp(x, hi, lo);
        size_t o = ((size_t)z * 128 + d0 + dl) * SQ + s0 + tx;
        vth[o] = hi; vtl[o] = lo;
    }
}

__global__ void softmax_kernel(float* __restrict__ attn, const float* __restrict__ bias,
                               bf16* __restrict__ ah, bf16* __restrict__ al,
                               int writeAttn)
{
    __shared__ float buf[2048];
    __shared__ float red[256];
    int qrow = blockIdx.x;
    long long base = (long long)blockIdx.y * SQ * SQ + (long long)qrow * SQ;
    float* row = attn + base;
    const float* brow = bias + (size_t)qrow * SQ;
    int L  = qrow + 1;
    int L4 = L & ~3;
    int tileEnd = ((qrow >> 7) + 1) << 7;
    int tid = threadIdx.x;

    float mx = -3.402823466e38f;
    for (int i = tid * 4; i < L4; i += 1024) {
        float4 r = *reinterpret_cast<const float4*>(row + i);
        float4 bb = *reinterpret_cast<const float4*>(brow + i);
        r.x += bb.x; r.y += bb.y; r.z += bb.z; r.w += bb.w;
        *reinterpret_cast<float4*>(buf + i) = r;
        mx = fmaxf(mx, fmaxf(fmaxf(r.x, r.y), fmaxf(r.z, r.w)));
    }
    for (int i = L4 + tid; i < L; i += 256) {
        float vv = row[i] + brow[i];
        buf[i] = vv;
        mx = fmaxf(mx, vv);
    }
    red[tid] = mx; __syncthreads();
    for (int o = 128; o; o >>= 1) {
        if (tid < o) red[tid] = fmaxf(red[tid], red[tid + o]);
        __syncthreads();
    }
    mx = red[0]; __syncthreads();

    float sum = 0.f;
    for (int i = tid; i < L; i += 256) {
        float e = __expf(buf[i] - mx);
        buf[i] = e;
        sum += e;
    }
    red[tid] = sum; __syncthreads();
    for (int o = 128; o; o >>= 1) {
        if (tid < o) red[tid] += red[tid + o];
        __syncthreads();
    }
    float inv = 1.0f / red[0];
    __syncthreads();

    for (int i = tid * 4; i < L4; i += 1024) {
        float a0 = buf[i]     * inv;
        float a1 = buf[i + 1] * inv;
        float a2 = buf[i + 2] * inv;
        float a3 = buf[i + 3] * inv;
        bf16 h0, l0, h1, l1, h2, l2, h3, l3;
        sp(a0, h0, l0); sp(a1, h1, l1); sp(a2, h2, l2); sp(a3, h3, l3);
        bf162 p; p.x = h0; p.y = h1;
        *reinterpret_cast<bf162*>(ah + base + i)     = p;
        p.x = h2; p.y = h3;
        *reinterpret_cast<bf162*>(ah + base + i + 2) = p;
        p.x = l0; p.y = l1;
        *reinterpret_cast<bf162*>(al + base + i)     = p;
        p.x = l2; p.y = l3;
        *reinterpret_cast<bf162*>(al + base + i + 2) = p;
        if (writeAttn)
            *reinterpret_cast<float4*>(row + i) = make_float4(a0, a1, a2, a3);
    }
    for (int i = L4 + tid; i < L; i += 256) {
        float a = buf[i] * inv;
        bf16 hi, lo; sp(a, hi, lo);
        ah[base + i] = hi; al[base + i] = lo;
        if (writeAttn) row[i] = a;
    }
    bf16 z16 = __float2bfloat16_rn(0.f);
    for (int i = L + tid; i < tileEnd; i += 256) { ah[base + i] = z16; al[base + i] = z16; }
    if (writeAttn)
        for (int i = L + tid; i < SQ; i += 256) row[i] = 0.f;
}

// =================================================================================
// Host launcher
// =================================================================================
extern "C" void kernel_launch(void* const* d_in, const int* in_sizes, int n_in,
                              void* d_out, int out_size)
{
    const float* x    = (const float*)d_in[0];
    const float* Wq   = (const float*)d_in[1];
    const float* Wk   = (const float*)d_in[2];
    const float* Wv   = (const float*)d_in[3];
    const float* Wo   = (const float*)d_in[4];
    const float* bias = (const float*)d_in[5];
    float* out = (float*)d_out;

    float *pqkv, *pao, *pbm, *pattn;
    bf16 *pxh, *pxl, *pwh, *pwl, *pwoh, *pwol;
    bf16 *pqh, *pql, *pkh, *pkl, *pvth, *pvtl, *paoh, *paol, *pah, *pal;
    cudaGetSymbolAddress((void**)&pqkv, g_qkv); cudaGetSymbolAddress((void**)&pao, g_ao);
    cudaGetSymbolAddress((void**)&pbm, g_bm);   cudaGetSymbolAddress((void**)&pattn, g_attn);
    cudaGetSymbolAddress((void**)&pxh, g_xh);   cudaGetSymbolAddress((void**)&pxl, g_xl);
    cudaGetSymbolAddress((void**)&pwh, g_wh);   cudaGetSymbolAddress((void**)&pwl, g_wl);
    cudaGetSymbolAddress((void**)&pwoh, g_woh); cudaGetSymbolAddress((void**)&pwol, g_wol);
    cudaGetSymbolAddress((void**)&pqh, g_qh);   cudaGetSymbolAddress((void**)&pql, g_ql);
    cudaGetSymbolAddress((void**)&pkh, g_kh);   cudaGetSymbolAddress((void**)&pkl, g_kl);
    cudaGetSymbolAddress((void**)&pvth, g_vth); cudaGetSymbolAddress((void**)&pvtl, g_vtl);
    cudaGetSymbolAddress((void**)&paoh, g_aoh); cudaGetSymbolAddress((void**)&paol, g_aol);
    cudaGetSymbolAddress((void**)&pah, g_ah);   cudaGetSymbolAddress((void**)&pal, g_al);

    const long long OUT_N = 8388608LL, ATT_N = 134217728LL;
    float* outPtr = out;
    float* attnPtr;
    int writeAttn = 1;
    long long osz = (long long)out_size;
    if (osz >= OUT_N + ATT_N) { attnPtr = out + OUT_N; }
    else if (osz == ATT_N)    { attnPtr = out; outPtr = pqkv; }
    else                      { attnPtr = pattn; writeAttn = 0; }

    const long long SH = (long long)SQ * HID;
    const long long SS = (long long)SQ * SQ;
    const long long WW = (long long)HID * HID;
    const long long QKVS = (long long)MR * HID;
    const int SMEM = 3 * 40960;    // 120 KB
    cudaFuncSetAttribute(mma_gemm, cudaFuncAttributeMaxDynamicSharedMemorySize, SMEM);

    split_kernel<<<8192, 256>>>(x,  pxh, pxl, 2097152);
    split_kernel<<<4096, 256>>>(Wq, pwh,        pwl,        1048576);
    split_kernel<<<4096, 256>>>(Wk, pwh + WW,   pwl + WW,   1048576);
    split_kernel<<<4096, 256>>>(Wv, pwh + 2*WW, pwl + 2*WW, 1048576);
    split_kernel<<<4096, 256>>>(Wo, pwoh, pwol, 1048576);

    // merged QKV projection
    dim3 gQKV(16, 32, 3);
    mma_gemm<<<gQKV, 256, SMEM>>>(pxh, pxl, pwh, pwl, pqkv, 2048, 2048, 2048, 2048,
                                  0, 0, WW, 0, QKVS, 0, 1, 1.0f, 0);

    bmean_kernel<<<SQ, 256>>>(bias, pbm);

    float* pq = pqkv;
    float* pk = pqkv + QKVS;
    float* pv = pqkv + 2 * QKVS;
    rope_split_kernel<<<16384, 256>>>(pq, pk, pbm, pqh, pql, pkh, pkl);
    vsplit_kernel<<<dim3(64, 4, 32), dim3(32, 8)>>>(pv, pvth, pvtl);

    // scores = q.k^T / sqrt(128), causal tile-skip
    dim3 gScore(16, 16, 32);
    mma_gemm<<<gScore, 256, SMEM>>>(pqh, pql, pkh, pkl, attnPtr, 128, 2048, 2048, 2048,
                                    SH, 128, SH, 128,
                                    16 * SS, SS, 16, 0.08838834764831845f, 1);

    softmax_kernel<<<dim3(SQ, 32), 256>>>(attnPtr, bias, pah, pal, writeAttn);

    // attn @ v, K-limited by causality; mode 2|4 = heavy-first y ordering
    dim3 gAV(1, 16, 32);
    mma_gemm<<<gAV, 256, SMEM>>>(pah, pal, pvth, pvtl, pao, 2048, 2048, 2048, 2048,
                                 16 * SS, SS, SH, (long long)128 * SQ,
                                 SH, 128, 16, 1.0f, 6);

    split_kernel<<<8192, 256>>>(pao, paoh, paol, 2097152);

    // output = attn_out @ Wo^T
    dim3 gProj(16, 32, 1);
    mma_gemm<<<gProj, 256, SMEM>>>(paoh, paol, pwoh, pwol, outPtr, 2048, 2048, 2048, 2048,
                                   0, 0, 0, 0, 0, 0, 1, 1.0f, 0);
}

// round 13
// speedup vs baseline: 1.1418x; 1.0859x over previous
#include <cuda_runtime.h>
#include <cuda_bf16.h>
#include <cuda_fp16.h>
#include <math.h>
#include <stdint.h>

#define SQ   2048
#define HID  2048
#define MR   4096

typedef __nv_bfloat16  bf16;
typedef __nv_bfloat162 bf162;

// ----------------------------- static scratch ------------------------------
__device__ float g_qkv[3u * MR * HID];
__device__ float g_ao [MR * HID];
__device__ float g_bm [SQ];
__device__ float g_attn[134217728];

__device__ bf16 g_xh [MR * HID],  g_xl [MR * HID];
__device__ bf16 g_wh [3u * HID * HID], g_wl[3u * HID * HID];
__device__ bf16 g_qh [MR * HID],  g_ql [MR * HID];
__device__ bf16 g_kh [MR * HID],  g_kl [MR * HID];

__device__ __half g_af  [134217728];             // attn fp16 (single)
__device__ __half g_vth [MR * HID], g_vtl[MR * HID];   // vT fp16 hi/lo
__device__ __half g_aof [MR * HID];              // ao fp16 (single)
__device__ __half g_wofh[HID * HID], g_wofl[HID * HID];// Wo fp16 hi/lo

// ----------------------------- helpers -------------------------------------
__device__ __forceinline__ uint32_t smem_u32(const void* p) {
    uint32_t a;
    asm("{ .reg .u64 t; cvta.to.shared.u64 t, %1; cvt.u32.u64 %0, t; }" : "=r"(a) : "l"(p));
    return a;
}
__device__ __forceinline__ void cp16(uint32_t dst, const void* src) {
    asm volatile("cp.async.cg.shared.global [%0], [%1], 16;" :: "r"(dst), "l"(src));
}
#define CP_COMMIT() asm volatile("cp.async.commit_group;" ::: "memory")
#define CP_WAIT(n)  asm volatile("cp.async.wait_group %0;" :: "n"(n) : "memory")

#define LDSM4(r0, r1, r2, r3, addr) \
    asm volatile("ldmatrix.sync.aligned.m8n8.x4.shared.b16 {%0,%1,%2,%3}, [%4];" \
        : "=r"(r0), "=r"(r1), "=r"(r2), "=r"(r3) : "r"(addr))

__device__ __forceinline__ void mma_bf16(float* c,
    uint32_t a0, uint32_t a1, uint32_t a2, uint32_t a3, uint32_t b0, uint32_t b1)
{
    asm volatile(
        "mma.sync.aligned.m16n8k16.row.col.f32.bf16.bf16.f32 "
        "{%0,%1,%2,%3}, {%4,%5,%6,%7}, {%8,%9}, {%0,%1,%2,%3};"
        : "+f"(c[0]), "+f"(c[1]), "+f"(c[2]), "+f"(c[3])
        : "r"(a0), "r"(a1), "r"(a2), "r"(a3), "r"(b0), "r"(b1));
}
__device__ __forceinline__ void mma_f16(float* c,
    uint32_t a0, uint32_t a1, uint32_t a2, uint32_t a3, uint32_t b0, uint32_t b1)
{
    asm volatile(
        "mma.sync.aligned.m16n8k16.row.col.f32.f16.f16.f32 "
        "{%0,%1,%2,%3}, {%4,%5,%6,%7}, {%8,%9}, {%0,%1,%2,%3};"
        : "+f"(c[0]), "+f"(c[1]), "+f"(c[2]), "+f"(c[3])
        : "r"(a0), "r"(a1), "r"(a2), "r"(a3), "r"(b0), "r"(b1));
}

// =================================================================================
// 3-pass split-bf16 NT GEMM (unchanged, proven): used for QKV + scores.
// =================================================================================
#define STG_BYTES 40960u
#define ARR_BYTES 10240u

__device__ __forceinline__ void load_stage32(
    uint32_t sbase, int slot, int k0,
    const bf16* __restrict__ Ah, const bf16* __restrict__ Al,
    const bf16* __restrict__ Bh, const bf16* __restrict__ Bl,
    int lda, int ldb, int rowBase, int colBase, int tid)
{
    uint32_t base = sbase + (uint32_t)slot * STG_BYTES;
    int r  = tid >> 1;
    int c0 = (tid & 1) << 1;
#pragma unroll
    for (int i = 0; i < 2; i++) {
        int c = c0 + i;
        uint32_t off = (uint32_t)(r * 40 + c * 8) * 2;
        const size_t ga = (size_t)(rowBase + r) * lda + k0 + c * 8;
        const size_t gb = (size_t)(colBase + r) * ldb + k0 + c * 8;
        cp16(base +                off, Ah + ga);
        cp16(base + ARR_BYTES    + off, Al + ga);
        cp16(base + 2u*ARR_BYTES + off, Bh + gb);
        cp16(base + 3u*ARR_BYTES + off, Bl + gb);
    }
    CP_COMMIT();
}

__global__ void __launch_bounds__(256, 1)
mma_gemm(const bf16* __restrict__ Ahi, const bf16* __restrict__ Alo,
         const bf16* __restrict__ Bhi, const bf16* __restrict__ Blo,
         float* __restrict__ C,
         int K, int lda, int ldb, int ldc,
         long long aSb, long long aSh, long long bSb, long long bSh,
         long long cSb, long long cSh, int nInner, float scale, int mode)
{
    extern __shared__ char smem[];
    const int z  = blockIdx.z;
    const int bb = z / nInner, hh = z - bb * nInner;
    const bf16* Ah = Ahi + bb * aSb + hh * aSh;
    const bf16* Al = Alo + bb * aSb + hh * aSh;
    const bf16* Bh = Bhi + bb * bSb + hh * bSh;
    const bf16* Bl = Blo + bb * bSb + hh * bSh;
    float* Cz = C + bb * cSb + hh * cSh;

    const int yIdx = (mode & 4) ? (gridDim.y - 1 - blockIdx.y) : blockIdx.y;
    const int rowBase = yIdx * 128;
    const int colBase = blockIdx.x * 128;
    if ((mode & 1) && colBase > rowBase + 127) return;
    int Keff = K;
    if (mode & 2) { int kl = rowBase + 128; Keff = kl < K ? kl : K; }
    const int nst = Keff >> 5;

    const uint32_t sb = smem_u32(smem);
    const int tid = threadIdx.x, lane = tid & 31, wid = tid >> 5;
    const int warpM = (wid & 1) << 6;
    const int warpN = (wid >> 1) << 5;

    const uint32_t offA = (uint32_t)((warpM + (lane & 15)) * 40
                                     + ((lane >> 4) << 3)) * 2;
    const uint32_t offB = (uint32_t)((warpN + (lane & 7) + ((lane >> 4) << 3)) * 40
                                     + (((lane >> 3) & 1) << 3)) * 2;

    float acc[4][4][4];
#pragma unroll
    for (int i = 0; i < 4; i++)
#pragma unroll
        for (int j = 0; j < 4; j++)
#pragma unroll
            for (int t = 0; t < 4; t++) acc[i][j][t] = 0.f;

    load_stage32(sb, 0, 0, Ah, Al, Bh, Bl, lda, ldb, rowBase, colBase, tid);
    if (nst > 1)
        load_stage32(sb, 1, 32, Ah, Al, Bh, Bl, lda, ldb, rowBase, colBase, tid);

    int slot = 0;
    for (int j = 0; j < nst; j++) {
        if (j + 2 < nst) {
            int ns = slot + 2; if (ns >= 3) ns -= 3;
            load_stage32(sb, ns, (j + 2) * 32, Ah, Al, Bh, Bl,
                         lda, ldb, rowBase, colBase, tid);
            CP_WAIT(2);
        } else if (j + 1 < nst) {
            CP_WAIT(1);
        } else {
            CP_WAIT(0);
        }
        __syncthreads();

        const uint32_t base = sb + (uint32_t)slot * STG_BYTES;
#pragma unroll
        for (int ks = 0; ks < 32; ks += 16) {
            uint32_t ah[4][4], al[4][4], bh[2][4], bl[2][4];
#pragma unroll
            for (int t = 0; t < 4; t++) {
                uint32_t ad = base + offA + (uint32_t)((t * 640 + ks) * 2);
                LDSM4(ah[t][0], ah[t][1], ah[t][2], ah[t][3], ad);
                LDSM4(al[t][0], al[t][1], al[t][2], al[t][3], ad + ARR_BYTES);
            }
#pragma unroll
            for (int g = 0; g < 2; g++) {
                uint32_t bd = base + 2u*ARR_BYTES + offB + (uint32_t)((g * 640 + ks) * 2);
                LDSM4(bh[g][0], bh[g][1], bh[g][2], bh[g][3], bd);
                LDSM4(bl[g][0], bl[g][1], bl[g][2], bl[g][3], bd + ARR_BYTES);
            }
#pragma unroll
            for (int mt = 0; mt < 4; mt++) {
#pragma unroll
                for (int g = 0; g < 2; g++) {
                    mma_bf16(acc[mt][2*g],   ah[mt][0], ah[mt][1], ah[mt][2], ah[mt][3], bh[g][0], bh[g][1]);
                    mma_bf16(acc[mt][2*g+1], ah[mt][0], ah[mt][1], ah[mt][2], ah[mt][3], bh[g][2], bh[g][3]);
                    mma_bf16(acc[mt][2*g],   ah[mt][0], ah[mt][1], ah[mt][2], ah[mt][3], bl[g][0], bl[g][1]);
                    mma_bf16(acc[mt][2*g+1], ah[mt][0], ah[mt][1], ah[mt][2], ah[mt][3], bl[g][2], bl[g][3]);
                    mma_bf16(acc[mt][2*g],   al[mt][0], al[mt][1], al[mt][2], al[mt][3], bh[g][0], bh[g][1]);
                    mma_bf16(acc[mt][2*g+1], al[mt][0], al[mt][1], al[mt][2], al[mt][3], bh[g][2], bh[g][3]);
                }
            }
        }
        __syncthreads();
        if (++slot >= 3) slot = 0;
    }

    const int row0 = rowBase + warpM + (lane >> 2);
    const int col0 = colBase + warpN + (lane & 3) * 2;
#pragma unroll
    for (int mt = 0; mt < 4; mt++) {
#pragma unroll
        for (int nt = 0; nt < 4; nt++) {
            float2 v0 = make_float2(acc[mt][nt][0] * scale, acc[mt][nt][1] * scale);
            float2 v1 = make_float2(acc[mt][nt][2] * scale, acc[mt][nt][3] * scale);
            size_t r0 = (size_t)(row0 + mt * 16) * ldc + col0 + nt * 8;
            *reinterpret_cast<float2*>(Cz + r0)                   = v0;
            *reinterpret_cast<float2*>(Cz + r0 + 8 * (size_t)ldc) = v1;
        }
    }
}

// =================================================================================
// 2-pass fp16 NT GEMM: C = scale * Af * (Bh + Bl)^T  (A single fp16, B split fp16).
// Same tile structure; 3 smem arrays per stage (30720 B), 32 MMA / ks-pair vs 48.
// Used for attn@v and out-proj (attn_weights path untouched).
// =================================================================================
#define ARR2 10240u
#define STG2 30720u

__device__ __forceinline__ void load_stage32f(
    uint32_t sbase, int slot, int k0,
    const __half* __restrict__ Af,
    const __half* __restrict__ Bh, const __half* __restrict__ Bl,
    int lda, int ldb, int rowBase, int colBase, int tid)
{
    uint32_t base = sbase + (uint32_t)slot * STG2;
    int r  = tid >> 1;
    int c0 = (tid & 1) << 1;
#pragma unroll
    for (int i = 0; i < 2; i++) {
        int c = c0 + i;
        uint32_t off = (uint32_t)(r * 40 + c * 8) * 2;
        const size_t ga = (size_t)(rowBase + r) * lda + k0 + c * 8;
        const size_t gb = (size_t)(colBase + r) * ldb + k0 + c * 8;
        cp16(base +           off, Af + ga);
        cp16(base + ARR2    + off, Bh + gb);
        cp16(base + 2u*ARR2 + off, Bl + gb);
    }
    CP_COMMIT();
}

__global__ void __launch_bounds__(256, 1)
mma_gemm2(const __half* __restrict__ Afi,
          const __half* __restrict__ Bhi, const __half* __restrict__ Bli,
          float* __restrict__ C,
          int K, int lda, int ldb, int ldc,
          long long aSb, long long aSh, long long bSb, long long bSh,
          long long cSb, long long cSh, int nInner, float scale, int mode)
{
    extern __shared__ char smem[];
    const int z  = blockIdx.z;
    const int bb = z / nInner, hh = z - bb * nInner;
    const __half* Af = Afi + bb * aSb + hh * aSh;
    const __half* Bh = Bhi + bb * bSb + hh * bSh;
    const __half* Bl = Bli + bb * bSb + hh * bSh;
    float* Cz = C + bb * cSb + hh * cSh;

    const int yIdx = (mode & 4) ? (gridDim.y - 1 - blockIdx.y) : blockIdx.y;
    const int rowBase = yIdx * 128;
    const int colBase = blockIdx.x * 128;
    if ((mode & 1) && colBase > rowBase + 127) return;
    int Keff = K;
    if (mode & 2) { int kl = rowBase + 128; Keff = kl < K ? kl : K; }
    const int nst = Keff >> 5;

    const uint32_t sb = smem_u32(smem);
    const int tid = threadIdx.x, lane = tid & 31, wid = tid >> 5;
    const int warpM = (wid & 1) << 6;
    const int warpN = (wid >> 1) << 5;

    const uint32_t offA = (uint32_t)((warpM + (lane & 15)) * 40
                                     + ((lane >> 4) << 3)) * 2;
    const uint32_t offB = (uint32_t)((warpN + (lane & 7) + ((lane >> 4) << 3)) * 40
                                     + (((lane >> 3) & 1) << 3)) * 2;

    float acc[4][4][4];
#pragma unroll
    for (int i = 0; i < 4; i++)
#pragma unroll
        for (int j = 0; j < 4; j++)
#pragma unroll
            for (int t = 0; t < 4; t++) acc[i][j][t] = 0.f;

    load_stage32f(sb, 0, 0, Af, Bh, Bl, lda, ldb, rowBase, colBase, tid);
    if (nst > 1)
        load_stage32f(sb, 1, 32, Af, Bh, Bl, lda, ldb, rowBase, colBase, tid);

    int slot = 0;
    for (int j = 0; j < nst; j++) {
        if (j + 2 < nst) {
            int ns = slot + 2; if (ns >= 3) ns -= 3;
            load_stage32f(sb, ns, (j + 2) * 32, Af, Bh, Bl,
                          lda, ldb, rowBase, colBase, tid);
            CP_WAIT(2);
        } else if (j + 1 < nst) {
            CP_WAIT(1);
        } else {
            CP_WAIT(0);
        }
        __syncthreads();

        const uint32_t base = sb + (uint32_t)slot * STG2;
#pragma unroll
        for (int ks = 0; ks < 32; ks += 16) {
            uint32_t af[4][4], bh[2][4], bl[2][4];
#pragma unroll
            for (int t = 0; t < 4; t++) {
                uint32_t ad = base + offA + (uint32_t)((t * 640 + ks) * 2);
                LDSM4(af[t][0], af[t][1], af[t][2], af[t][3], ad);
            }
#pragma unroll
            for (int g = 0; g < 2; g++) {
                uint32_t bd = base + ARR2 + offB + (uint32_t)((g * 640 + ks) * 2);
                LDSM4(bh[g][0], bh[g][1], bh[g][2], bh[g][3], bd);
                LDSM4(bl[g][0], bl[g][1], bl[g][2], bl[g][3], bd + ARR2);
            }
#pragma unroll
            for (int mt = 0; mt < 4; mt++) {
#pragma unroll
                for (int g = 0; g < 2; g++) {
                    mma_f16(acc[mt][2*g],   af[mt][0], af[mt][1], af[mt][2], af[mt][3], bh[g][0], bh[g][1]);
                    mma_f16(acc[mt][2*g+1], af[mt][0], af[mt][1], af[mt][2], af[mt][3], bh[g][2], bh[g][3]);
                    mma_f16(acc[mt][2*g],   af[mt][0], af[mt][1], af[mt][2], af[mt][3], bl[g][0], bl[g][1]);
                    mma_f16(acc[mt][2*g+1], af[mt][0], af[mt][1], af[mt][2], af[mt][3], bl[g][2], bl[g][3]);
                }
            }
        }
        __syncthreads();
        if (++slot >= 3) slot = 0;
    }

    const int row0 = rowBase + warpM + (lane >> 2);
    const int col0 = colBase + warpN + (lane & 3) * 2;
#pragma unroll
    for (int mt = 0; mt < 4; mt++) {
#pragma unroll
        for (int nt = 0; nt < 4; nt++) {
            float2 v0 = make_float2(acc[mt][nt][0] * scale, acc[mt][nt][1] * scale);
            float2 v1 = make_float2(acc[mt][nt][2] * scale, acc[mt][nt][3] * scale);
            size_t r0 = (size_t)(row0 + mt * 16) * ldc + col0 + nt * 8;
            *reinterpret_cast<float2*>(Cz + r0)                   = v0;
            *reinterpret_cast<float2*>(Cz + r0 + 8 * (size_t)ldc) = v1;
        }
    }
}

// =================================================================================
// Elementwise kernels
// =================================================================================
__device__ __forceinline__ void sp(float v, bf16& h, bf16& l) {
    h = __float2bfloat16_rn(v);
    l = __float2bfloat16_rn(v - __bfloat162float(h));
}
__device__ __forceinline__ void sph(float v, __half& h, __half& l) {
    h = __float2half_rn(v);
    l = __float2half_rn(v - __half2float(h));
}

__global__ void split_kernel(const float* __restrict__ in,
                             bf16* __restrict__ hi, bf16* __restrict__ lo, int n4)
{
    int i = blockIdx.x * 256 + threadIdx.x;
    if (i >= n4) return;
    float4 v = reinterpret_cast<const float4*>(in)[i];
    bf16 h0, l0, h1, l1, h2, l2, h3, l3;
    sp(v.x, h0, l0); sp(v.y, h1, l1); sp(v.z, h2, l2); sp(v.w, h3, l3);
    bf162 a, b;
    a.x = h0; a.y = h1; b.x = h2; b.y = h3;
    reinterpret_cast<bf162*>(hi)[i * 2] = a; reinterpret_cast<bf162*>(hi)[i * 2 + 1] = b;
    a.x = l0; a.y = l1; b.x = l2; b.y = l3;
    reinterpret_cast<bf162*>(lo)[i * 2] = a; reinterpret_cast<bf162*>(lo)[i * 2 + 1] = b;
}

// float -> fp16 hi/lo (for Wo)
__global__ void splitf2_kernel(const float* __restrict__ in,
                               __half* __restrict__ hi, __half* __restrict__ lo, int n4)
{
    int i = blockIdx.x * 256 + threadIdx.x;
    if (i >= n4) return;
    float4 v = reinterpret_cast<const float4*>(in)[i];
    __half h0, l0, h1, l1, h2, l2, h3, l3;
    sph(v.x, h0, l0); sph(v.y, h1, l1); sph(v.z, h2, l2); sph(v.w, h3, l3);
    reinterpret_cast<__half2*>(hi)[i * 2]     = __halves2half2(h0, h1);
    reinterpret_cast<__half2*>(hi)[i * 2 + 1] = __halves2half2(h2, h3);
    reinterpret_cast<__half2*>(lo)[i * 2]     = __halves2half2(l0, l1);
    reinterpret_cast<__half2*>(lo)[i * 2 + 1] = __halves2half2(l2, l3);
}

// float -> fp16 single (for ao)
__global__ void splitf1_kernel(const float* __restrict__ in,
                               __half* __restrict__ f, int n4)
{
    int i = blockIdx.x * 256 + threadIdx.x;
    if (i >= n4) return;
    float4 v = reinterpret_cast<const float4*>(in)[i];
    reinterpret_cast<__half2*>(f)[i * 2]     = __halves2half2(__float2half_rn(v.x), __float2half_rn(v.y));
    reinterpret_cast<__half2*>(f)[i * 2 + 1] = __halves2half2(__float2half_rn(v.z), __float2half_rn(v.w));
}

__global__ void bmean_kernel(const float* __restrict__ bias, float* __restrict__ bm)
{
    __shared__ float red[256];
    int r = blockIdx.x;
    const float* row = bias + (size_t)r * SQ;
    float s = 0.f;
    for (int i = threadIdx.x; i < SQ; i += 256) s += row[i];
    red[threadIdx.x] = s; __syncthreads();
    for (int o = 128; o; o >>= 1) {
        if (threadIdx.x < o) red[threadIdx.x] += red[threadIdx.x + o];
        __syncthreads();
    }
    if (threadIdx.x == 0) bm[r] = red[0] * (0.1f / 2048.0f);
}

__global__ void rope_split_kernel(const float* __restrict__ q, const float* __restrict__ k,
                                  const float* __restrict__ bm,
                                  bf16* __restrict__ qh, bf16* __restrict__ ql,
                                  bf16* __restrict__ kh, bf16* __restrict__ kl)
{
    __shared__ float sinvf[64];
    if (threadIdx.x < 64)
        sinvf[threadIdx.x] =
            (float)exp(-((double)(2 * threadIdx.x) / 128.0) * log(10000.0));
    __syncthreads();

    int idx = blockIdx.x * 256 + threadIdx.x;
    int d2 = idx & 63;
    int h  = (idx >> 6) & 15;
    int m  = idx >> 10;
    int s  = m & (SQ - 1);

    float sn, cs;
    sincosf((float)s * sinvf[d2], &sn, &cs);
    float b = bm[s];

    size_t off = (size_t)m * HID + (size_t)h * 128 + d2;
    float q0 = q[off], q1 = q[off + 64];
    float k0 = k[off], k1 = k[off + 64];
    float qa = q0 * cs - q1 * sn + b;
    float qb = q1 * cs + q0 * sn + b;
    float ka = k0 * cs - k1 * sn + b;
    float kb = k1 * cs + k0 * sn + b;
    bf16 h_, l_;
    sp(qa, h_, l_); qh[off]      = h_; ql[off]      = l_;
    sp(qb, h_, l_); qh[off + 64] = h_; ql[off + 64] = l_;
    sp(ka, h_, l_); kh[off]      = h_; kl[off]      = l_;
    sp(kb, h_, l_); kh[off + 64] = h_; kl[off + 64] = l_;
}

// v fp32 -> vT fp16 hi/lo [(b*16+h)*128+d][s]
__global__ void vsplit_kernel(const float* __restrict__ v,
                              __half* __restrict__ vth, __half* __restrict__ vtl)
{
    __shared__ float t[32][33];
    int z = blockIdx.z, b = z >> 4, h = z & 15;
    int s0 = blockIdx.x * 32, d0 = blockIdx.y * 32;
    int tx = threadIdx.x, ty = threadIdx.y;
#pragma unroll
    for (int i = 0; i < 4; i++) {
        int sl = ty * 4 + i;
        t[sl][tx] = v[(size_t)(b * SQ + s0 + sl) * HID + h * 128 + d0 + tx];
    }
    __syncthreads();
#pragma unroll
    for (int i = 0; i < 4; i++) {
        int dl = ty * 4 + i;
        float x = t[tx][dl];
        __half hi, lo; sph(x, hi, lo);
        size_t o = ((size_t)z * 128 + d0 + dl) * SQ + s0 + tx;
        vth[o] = hi; vtl[o] = lo;
    }
}

// causal softmax with bias; writes fp16 single attn for AV + fp32 (if output).
__global__ void softmax_kernel(float* __restrict__ attn, const float* __restrict__ bias,
                               __half* __restrict__ af, int writeAttn)
{
    __shared__ float buf[2048];
    __shared__ float red[256];
    int qrow = blockIdx.x;
    long long base = (long long)blockIdx.y * SQ * SQ + (long long)qrow * SQ;
    float* row = attn + base;
    const float* brow = bias + (size_t)qrow * SQ;
    int L  = qrow + 1;
    int L4 = L & ~3;
    int tileEnd = ((qrow >> 7) + 1) << 7;
    int tid = threadIdx.x;

    float mx = -3.402823466e38f;
    for (int i = tid * 4; i < L4; i += 1024) {
        float4 r = *reinterpret_cast<const float4*>(row + i);
        float4 bb = *reinterpret_cast<const float4*>(brow + i);
        r.x += bb.x; r.y += bb.y; r.z += bb.z; r.w += bb.w;
        *reinterpret_cast<float4*>(buf + i) = r;
        mx = fmaxf(mx, fmaxf(fmaxf(r.x, r.y), fmaxf(r.z, r.w)));
    }
    for (int i = L4 + tid; i < L; i += 256) {
        float vv = row[i] + brow[i];
        buf[i] = vv;
        mx = fmaxf(mx, vv);
    }
    red[tid] = mx; __syncthreads();
    for (int o = 128; o; o >>= 1) {
        if (tid < o) red[tid] = fmaxf(red[tid], red[tid + o]);
        __syncthreads();
    }
    mx = red[0]; __syncthreads();

    float sum = 0.f;
    for (int i = tid; i < L; i += 256) {
        float e = __expf(buf[i] - mx);
        buf[i] = e;
        sum += e;
    }
    red[tid] = sum; __syncthreads();
    for (int o = 128; o; o >>= 1) {
        if (tid < o) red[tid] += red[tid + o];
        __syncthreads();
    }
    float inv = 1.0f / red[0];
    __syncthreads();

    for (int i = tid * 4; i < L4; i += 1024) {
        float a0 = buf[i]     * inv;
        float a1 = buf[i + 1] * inv;
        float a2 = buf[i + 2] * inv;
        float a3 = buf[i + 3] * inv;
        *reinterpret_cast<__half2*>(af + base + i)     =
            __halves2half2(__float2half_rn(a0), __float2half_rn(a1));
        *reinterpret_cast<__half2*>(af + base + i + 2) =
            __halves2half2(__float2half_rn(a2), __float2half_rn(a3));
        if (writeAttn)
            *reinterpret_cast<float4*>(row + i) = make_float4(a0, a1, a2, a3);
    }
    for (int i = L4 + tid; i < L; i += 256) {
        float a = buf[i] * inv;
        af[base + i] = __float2half_rn(a);
        if (writeAttn) row[i] = a;
    }
    __half z16 = __float2half_rn(0.f);
    for (int i = L + tid; i < tileEnd; i += 256) af[base + i] = z16;
    if (writeAttn)
        for (int i = L + tid; i < SQ; i += 256) row[i] = 0.f;
}

// =================================================================================
// Host launcher
// =================================================================================
extern "C" void kernel_launch(void* const* d_in, const int* in_sizes, int n_in,
                              void* d_out, int out_size)
{
    const float* x    = (const float*)d_in[0];
    const float* Wq   = (const float*)d_in[1];
    const float* Wk   = (const float*)d_in[2];
    const float* Wv   = (const float*)d_in[3];
    const float* Wo   = (const float*)d_in[4];
    const float* bias = (const float*)d_in[5];
    float* out = (float*)d_out;

    float *pqkv, *pao, *pbm, *pattn;
    bf16 *pxh, *pxl, *pwh, *pwl, *pqh, *pql, *pkh, *pkl;
    __half *paf, *pvth, *pvtl, *paof, *pwofh, *pwofl;
    cudaGetSymbolAddress((void**)&pqkv, g_qkv); cudaGetSymbolAddress((void**)&pao, g_ao);
    cudaGetSymbolAddress((void**)&pbm, g_bm);   cudaGetSymbolAddress((void**)&pattn, g_attn);
    cudaGetSymbolAddress((void**)&pxh, g_xh);   cudaGetSymbolAddress((void**)&pxl, g_xl);
    cudaGetSymbolAddress((void**)&pwh, g_wh);   cudaGetSymbolAddress((void**)&pwl, g_wl);
    cudaGetSymbolAddress((void**)&pqh, g_qh);   cudaGetSymbolAddress((void**)&pql, g_ql);
    cudaGetSymbolAddress((void**)&pkh, g_kh);   cudaGetSymbolAddress((void**)&pkl, g_kl);
    cudaGetSymbolAddress((void**)&paf, g_af);
    cudaGetSymbolAddress((void**)&pvth, g_vth); cudaGetSymbolAddress((void**)&pvtl, g_vtl);
    cudaGetSymbolAddress((void**)&paof, g_aof);
    cudaGetSymbolAddress((void**)&pwofh, g_wofh); cudaGetSymbolAddress((void**)&pwofl, g_wofl);

    const long long OUT_N = 8388608LL, ATT_N = 134217728LL;
    float* outPtr = out;
    float* attnPtr;
    int writeAttn = 1;
    long long osz = (long long)out_size;
    if (osz >= OUT_N + ATT_N) { attnPtr = out + OUT_N; }
    else if (osz == ATT_N)    { attnPtr = out; outPtr = pqkv; }
    else                      { attnPtr = pattn; writeAttn = 0; }

    const long long SH = (long long)SQ * HID;
    const long long SS = (long long)SQ * SQ;
    const long long WW = (long long)HID * HID;
    const long long QKVS = (long long)MR * HID;
    const int SMEM  = 3 * 40960;
    const int SMEM2 = 3 * 30720;
    cudaFuncSetAttribute(mma_gemm,  cudaFuncAttributeMaxDynamicSharedMemorySize, SMEM);
    cudaFuncSetAttribute(mma_gemm2, cudaFuncAttributeMaxDynamicSharedMemorySize, SMEM2);

    split_kernel<<<8192, 256>>>(x,  pxh, pxl, 2097152);
    split_kernel<<<4096, 256>>>(Wq, pwh,        pwl,        1048576);
    split_kernel<<<4096, 256>>>(Wk, pwh + WW,   pwl + WW,   1048576);
    split_kernel<<<4096, 256>>>(Wv, pwh + 2*WW, pwl + 2*WW, 1048576);
    splitf2_kernel<<<4096, 256>>>(Wo, pwofh, pwofl, 1048576);

    // merged QKV projection (3-pass bf16)
    dim3 gQKV(16, 32, 3);
    mma_gemm<<<gQKV, 256, SMEM>>>(pxh, pxl, pwh, pwl, pqkv, 2048, 2048, 2048, 2048,
                                  0, 0, WW, 0, QKVS, 0, 1, 1.0f, 0);

    bmean_kernel<<<SQ, 256>>>(bias, pbm);

    float* pq = pqkv;
    float* pk = pqkv + QKVS;
    float* pv = pqkv + 2 * QKVS;
    rope_split_kernel<<<16384, 256>>>(pq, pk, pbm, pqh, pql, pkh, pkl);
    vsplit_kernel<<<dim3(64, 4, 32), dim3(32, 8)>>>(pv, pvth, pvtl);

    // scores = q.k^T / sqrt(128), causal tile-skip (3-pass bf16, exact path kept)
    dim3 gScore(16, 16, 32);
    mma_gemm<<<gScore, 256, SMEM>>>(pqh, pql, pkh, pkl, attnPtr, 128, 2048, 2048, 2048,
                                    SH, 128, SH, 128,
                                    16 * SS, SS, 16, 0.08838834764831845f, 1);

    softmax_kernel<<<dim3(SQ, 32), 256>>>(attnPtr, bias, paf, writeAttn);

    // attn @ v : 2-pass fp16 (A = attn single, B = vT hi/lo), K-limited, heavy-first
    dim3 gAV(1, 16, 32);
    mma_gemm2<<<gAV, 256, SMEM2>>>(paf, pvth, pvtl, pao, 2048, 2048, 2048, 2048,
                                   16 * SS, SS, SH, (long long)128 * SQ,
                                   SH, 128, 16, 1.0f, 6);

    splitf1_kernel<<<8192, 256>>>(pao, paof, 2097152);

    // output = attn_out @ Wo^T : 2-pass fp16
    dim3 gProj(16, 32, 1);
    mma_gemm2<<<gProj, 256, SMEM2>>>(paof, pwofh, pwofl, outPtr, 2048, 2048, 2048, 2048,
                                     0, 0, 0, 0, 0, 0, 1, 1.0f, 0);
}

// round 14
// speedup vs baseline: 1.3175x; 1.1539x over previous
#include <cuda_runtime.h>
#include <cuda_bf16.h>
#include <cuda_fp16.h>
#include <math.h>
#include <stdint.h>

#define SQ   2048
#define HID  2048
#define MR   4096

typedef __nv_bfloat16  bf16;
typedef __nv_bfloat162 bf162;

// ----------------------------- static scratch ------------------------------
__device__ float g_qkv[3u * MR * HID];
__device__ float g_ao [MR * HID];
__device__ float g_bm [SQ];
__device__ float g_attn[134217728];

__device__ bf16 g_qh [MR * HID],  g_ql [MR * HID];
__device__ bf16 g_kh [MR * HID],  g_kl [MR * HID];

__device__ __half g_xf  [MR * HID];                    // x fp16 (single)
__device__ __half g_wfh [3u * HID * HID];              // Wq,Wk,Wv fp16 hi
__device__ __half g_wfl [3u * HID * HID];              // Wq,Wk,Wv fp16 lo
__device__ __half g_af  [134217728];                   // attn fp16 (single)
__device__ __half g_vth [MR * HID], g_vtl[MR * HID];   // vT fp16 hi/lo
__device__ __half g_aof [MR * HID];                    // ao fp16 (single)
__device__ __half g_wofh[HID * HID], g_wofl[HID * HID];// Wo fp16 hi/lo

// ----------------------------- helpers -------------------------------------
__device__ __forceinline__ uint32_t smem_u32(const void* p) {
    uint32_t a;
    asm("{ .reg .u64 t; cvta.to.shared.u64 t, %1; cvt.u32.u64 %0, t; }" : "=r"(a) : "l"(p));
    return a;
}
__device__ __forceinline__ void cp16(uint32_t dst, const void* src) {
    asm volatile("cp.async.cg.shared.global [%0], [%1], 16;" :: "r"(dst), "l"(src));
}
#define CP_COMMIT() asm volatile("cp.async.commit_group;" ::: "memory")
#define CP_WAIT(n)  asm volatile("cp.async.wait_group %0;" :: "n"(n) : "memory")

#define LDSM4(r0, r1, r2, r3, addr) \
    asm volatile("ldmatrix.sync.aligned.m8n8.x4.shared.b16 {%0,%1,%2,%3}, [%4];" \
        : "=r"(r0), "=r"(r1), "=r"(r2), "=r"(r3) : "r"(addr))

__device__ __forceinline__ void mma_bf16(float* c,
    uint32_t a0, uint32_t a1, uint32_t a2, uint32_t a3, uint32_t b0, uint32_t b1)
{
    asm volatile(
        "mma.sync.aligned.m16n8k16.row.col.f32.bf16.bf16.f32 "
        "{%0,%1,%2,%3}, {%4,%5,%6,%7}, {%8,%9}, {%0,%1,%2,%3};"
        : "+f"(c[0]), "+f"(c[1]), "+f"(c[2]), "+f"(c[3])
        : "r"(a0), "r"(a1), "r"(a2), "r"(a3), "r"(b0), "r"(b1));
}
__device__ __forceinline__ void mma_f16(float* c,
    uint32_t a0, uint32_t a1, uint32_t a2, uint32_t a3, uint32_t b0, uint32_t b1)
{
    asm volatile(
        "mma.sync.aligned.m16n8k16.row.col.f32.f16.f16.f32 "
        "{%0,%1,%2,%3}, {%4,%5,%6,%7}, {%8,%9}, {%0,%1,%2,%3};"
        : "+f"(c[0]), "+f"(c[1]), "+f"(c[2]), "+f"(c[3])
        : "r"(a0), "r"(a1), "r"(a2), "r"(a3), "r"(b0), "r"(b1));
}

// =================================================================================
// 3-pass split-bf16 NT GEMM (exact path): used for scores only.
// =================================================================================
#define STG_BYTES 40960u
#define ARR_BYTES 10240u

__device__ __forceinline__ void load_stage32(
    uint32_t sbase, int slot, int k0,
    const bf16* __restrict__ Ah, const bf16* __restrict__ Al,
    const bf16* __restrict__ Bh, const bf16* __restrict__ Bl,
    int lda, int ldb, int rowBase, int colBase, int tid)
{
    uint32_t base = sbase + (uint32_t)slot * STG_BYTES;
    int r  = tid >> 1;
    int c0 = (tid & 1) << 1;
#pragma unroll
    for (int i = 0; i < 2; i++) {
        int c = c0 + i;
        uint32_t off = (uint32_t)(r * 40 + c * 8) * 2;
        const size_t ga = (size_t)(rowBase + r) * lda + k0 + c * 8;
        const size_t gb = (size_t)(colBase + r) * ldb + k0 + c * 8;
        cp16(base +                off, Ah + ga);
        cp16(base + ARR_BYTES    + off, Al + ga);
        cp16(base + 2u*ARR_BYTES + off, Bh + gb);
        cp16(base + 3u*ARR_BYTES + off, Bl + gb);
    }
    CP_COMMIT();
}

__global__ void __launch_bounds__(256, 1)
mma_gemm(const bf16* __restrict__ Ahi, const bf16* __restrict__ Alo,
         const bf16* __restrict__ Bhi, const bf16* __restrict__ Blo,
         float* __restrict__ C,
         int K, int lda, int ldb, int ldc,
         long long aSb, long long aSh, long long bSb, long long bSh,
         long long cSb, long long cSh, int nInner, float scale, int mode)
{
    extern __shared__ char smem[];
    const int z  = blockIdx.z;
    const int bb = z / nInner, hh = z - bb * nInner;
    const bf16* Ah = Ahi + bb * aSb + hh * aSh;
    const bf16* Al = Alo + bb * aSb + hh * aSh;
    const bf16* Bh = Bhi + bb * bSb + hh * bSh;
    const bf16* Bl = Blo + bb * bSb + hh * bSh;
    float* Cz = C + bb * cSb + hh * cSh;

    const int yIdx = (mode & 4) ? (gridDim.y - 1 - blockIdx.y) : blockIdx.y;
    const int rowBase = yIdx * 128;
    const int colBase = blockIdx.x * 128;
    if ((mode & 1) && colBase > rowBase + 127) return;
    int Keff = K;
    if (mode & 2) { int kl = rowBase + 128; Keff = kl < K ? kl : K; }
    const int nst = Keff >> 5;

    const uint32_t sb = smem_u32(smem);
    const int tid = threadIdx.x, lane = tid & 31, wid = tid >> 5;
    const int warpM = (wid & 1) << 6;
    const int warpN = (wid >> 1) << 5;

    const uint32_t offA = (uint32_t)((warpM + (lane & 15)) * 40
                                     + ((lane >> 4) << 3)) * 2;
    const uint32_t offB = (uint32_t)((warpN + (lane & 7) + ((lane >> 4) << 3)) * 40
                                     + (((lane >> 3) & 1) << 3)) * 2;

    float acc[4][4][4];
#pragma unroll
    for (int i = 0; i < 4; i++)
#pragma unroll
        for (int j = 0; j < 4; j++)
#pragma unroll
            for (int t = 0; t < 4; t++) acc[i][j][t] = 0.f;

    load_stage32(sb, 0, 0, Ah, Al, Bh, Bl, lda, ldb, rowBase, colBase, tid);
    if (nst > 1)
        load_stage32(sb, 1, 32, Ah, Al, Bh, Bl, lda, ldb, rowBase, colBase, tid);

    int slot = 0;
    for (int j = 0; j < nst; j++) {
        if (j + 2 < nst) {
            int ns = slot + 2; if (ns >= 3) ns -= 3;
            load_stage32(sb, ns, (j + 2) * 32, Ah, Al, Bh, Bl,
                         lda, ldb, rowBase, colBase, tid);
            CP_WAIT(2);
        } else if (j + 1 < nst) {
            CP_WAIT(1);
        } else {
            CP_WAIT(0);
        }
        __syncthreads();

        const uint32_t base = sb + (uint32_t)slot * STG_BYTES;
#pragma unroll
        for (int ks = 0; ks < 32; ks += 16) {
            uint32_t ah[4][4], al[4][4], bh[2][4], bl[2][4];
#pragma unroll
            for (int t = 0; t < 4; t++) {
                uint32_t ad = base + offA + (uint32_t)((t * 640 + ks) * 2);
                LDSM4(ah[t][0], ah[t][1], ah[t][2], ah[t][3], ad);
                LDSM4(al[t][0], al[t][1], al[t][2], al[t][3], ad + ARR_BYTES);
            }
#pragma unroll
            for (int g = 0; g < 2; g++) {
                uint32_t bd = base + 2u*ARR_BYTES + offB + (uint32_t)((g * 640 + ks) * 2);
                LDSM4(bh[g][0], bh[g][1], bh[g][2], bh[g][3], bd);
                LDSM4(bl[g][0], bl[g][1], bl[g][2], bl[g][3], bd + ARR_BYTES);
            }
#pragma unroll
            for (int mt = 0; mt < 4; mt++) {
#pragma unroll
                for (int g = 0; g < 2; g++) {
                    mma_bf16(acc[mt][2*g],   ah[mt][0], ah[mt][1], ah[mt][2], ah[mt][3], bh[g][0], bh[g][1]);
                    mma_bf16(acc[mt][2*g+1], ah[mt][0], ah[mt][1], ah[mt][2], ah[mt][3], bh[g][2], bh[g][3]);
                    mma_bf16(acc[mt][2*g],   ah[mt][0], ah[mt][1], ah[mt][2], ah[mt][3], bl[g][0], bl[g][1]);
                    mma_bf16(acc[mt][2*g+1], ah[mt][0], ah[mt][1], ah[mt][2], ah[mt][3], bl[g][2], bl[g][3]);
                    mma_bf16(acc[mt][2*g],   al[mt][0], al[mt][1], al[mt][2], al[mt][3], bh[g][0], bh[g][1]);
                    mma_bf16(acc[mt][2*g+1], al[mt][0], al[mt][1], al[mt][2], al[mt][3], bh[g][2], bh[g][3]);
                }
            }
        }
        __syncthreads();
        if (++slot >= 3) slot = 0;
    }

    const int row0 = rowBase + warpM + (lane >> 2);
    const int col0 = colBase + warpN + (lane & 3) * 2;
#pragma unroll
    for (int mt = 0; mt < 4; mt++) {
#pragma unroll
        for (int nt = 0; nt < 4; nt++) {
            float2 v0 = make_float2(acc[mt][nt][0] * scale, acc[mt][nt][1] * scale);
            float2 v1 = make_float2(acc[mt][nt][2] * scale, acc[mt][nt][3] * scale);
            size_t r0 = (size_t)(row0 + mt * 16) * ldc + col0 + nt * 8;
            *reinterpret_cast<float2*>(Cz + r0)                   = v0;
            *reinterpret_cast<float2*>(Cz + r0 + 8 * (size_t)ldc) = v1;
        }
    }
}

// =================================================================================
// 2-pass fp16 NT GEMM: C = scale * Af * (Bh + Bl)^T.
// Used for QKV, attn@v, out-proj.
// =================================================================================
#define ARR2 10240u
#define STG2 30720u

__device__ __forceinline__ void load_stage32f(
    uint32_t sbase, int slot, int k0,
    const __half* __restrict__ Af,
    const __half* __restrict__ Bh, const __half* __restrict__ Bl,
    int lda, int ldb, int rowBase, int colBase, int tid)
{
    uint32_t base = sbase + (uint32_t)slot * STG2;
    int r  = tid >> 1;
    int c0 = (tid & 1) << 1;
#pragma unroll
    for (int i = 0; i < 2; i++) {
        int c = c0 + i;
        uint32_t off = (uint32_t)(r * 40 + c * 8) * 2;
        const size_t ga = (size_t)(rowBase + r) * lda + k0 + c * 8;
        const size_t gb = (size_t)(colBase + r) * ldb + k0 + c * 8;
        cp16(base +           off, Af + ga);
        cp16(base + ARR2    + off, Bh + gb);
        cp16(base + 2u*ARR2 + off, Bl + gb);
    }
    CP_COMMIT();
}

__global__ void __launch_bounds__(256, 1)
mma_gemm2(const __half* __restrict__ Afi,
          const __half* __restrict__ Bhi, const __half* __restrict__ Bli,
          float* __restrict__ C,
          int K, int lda, int ldb, int ldc,
          long long aSb, long long aSh, long long bSb, long long bSh,
          long long cSb, long long cSh, int nInner, float scale, int mode)
{
    extern __shared__ char smem[];
    const int z  = blockIdx.z;
    const int bb = z / nInner, hh = z - bb * nInner;
    const __half* Af = Afi + bb * aSb + hh * aSh;
    const __half* Bh = Bhi + bb * bSb + hh * bSh;
    const __half* Bl = Bli + bb * bSb + hh * bSh;
    float* Cz = C + bb * cSb + hh * cSh;

    const int yIdx = (mode & 4) ? (gridDim.y - 1 - blockIdx.y) : blockIdx.y;
    const int rowBase = yIdx * 128;
    const int colBase = blockIdx.x * 128;
    if ((mode & 1) && colBase > rowBase + 127) return;
    int Keff = K;
    if (mode & 2) { int kl = rowBase + 128; Keff = kl < K ? kl : K; }
    const int nst = Keff >> 5;

    const uint32_t sb = smem_u32(smem);
    const int tid = threadIdx.x, lane = tid & 31, wid = tid >> 5;
    const int warpM = (wid & 1) << 6;
    const int warpN = (wid >> 1) << 5;

    const uint32_t offA = (uint32_t)((warpM + (lane & 15)) * 40
                                     + ((lane >> 4) << 3)) * 2;
    const uint32_t offB = (uint32_t)((warpN + (lane & 7) + ((lane >> 4) << 3)) * 40
                                     + (((lane >> 3) & 1) << 3)) * 2;

    float acc[4][4][4];
#pragma unroll
    for (int i = 0; i < 4; i++)
#pragma unroll
        for (int j = 0; j < 4; j++)
#pragma unroll
            for (int t = 0; t < 4; t++) acc[i][j][t] = 0.f;

    load_stage32f(sb, 0, 0, Af, Bh, Bl, lda, ldb, rowBase, colBase, tid);
    if (nst > 1)
        load_stage32f(sb, 1, 32, Af, Bh, Bl, lda, ldb, rowBase, colBase, tid);

    int slot = 0;
    for (int j = 0; j < nst; j++) {
        if (j + 2 < nst) {
            int ns = slot + 2; if (ns >= 3) ns -= 3;
            load_stage32f(sb, ns, (j + 2) * 32, Af, Bh, Bl,
                          lda, ldb, rowBase, colBase, tid);
            CP_WAIT(2);
        } else if (j + 1 < nst) {
            CP_WAIT(1);
        } else {
            CP_WAIT(0);
        }
        __syncthreads();

        const uint32_t base = sb + (uint32_t)slot * STG2;
#pragma unroll
        for (int ks = 0; ks < 32; ks += 16) {
            uint32_t af[4][4], bh[2][4], bl[2][4];
#pragma unroll
            for (int t = 0; t < 4; t++) {
                uint32_t ad = base + offA + (uint32_t)((t * 640 + ks) * 2);
                LDSM4(af[t][0], af[t][1], af[t][2], af[t][3], ad);
            }
#pragma unroll
            for (int g = 0; g < 2; g++) {
                uint32_t bd = base + ARR2 + offB + (uint32_t)((g * 640 + ks) * 2);
                LDSM4(bh[g][0], bh[g][1], bh[g][2], bh[g][3], bd);
                LDSM4(bl[g][0], bl[g][1], bl[g][2], bl[g][3], bd + ARR2);
            }
#pragma unroll
            for (int mt = 0; mt < 4; mt++) {
#pragma unroll
                for (int g = 0; g < 2; g++) {
                    mma_f16(acc[mt][2*g],   af[mt][0], af[mt][1], af[mt][2], af[mt][3], bh[g][0], bh[g][1]);
                    mma_f16(acc[mt][2*g+1], af[mt][0], af[mt][1], af[mt][2], af[mt][3], bh[g][2], bh[g][3]);
                    mma_f16(acc[mt][2*g],   af[mt][0], af[mt][1], af[mt][2], af[mt][3], bl[g][0], bl[g][1]);
                    mma_f16(acc[mt][2*g+1], af[mt][0], af[mt][1], af[mt][2], af[mt][3], bl[g][2], bl[g][3]);
                }
            }
        }
        __syncthreads();
        if (++slot >= 3) slot = 0;
    }

    const int row0 = rowBase + warpM + (lane >> 2);
    const int col0 = colBase + warpN + (lane & 3) * 2;
#pragma unroll
    for (int mt = 0; mt < 4; mt++) {
#pragma unroll
        for (int nt = 0; nt < 4; nt++) {
            float2 v0 = make_float2(acc[mt][nt][0] * scale, acc[mt][nt][1] * scale);
            float2 v1 = make_float2(acc[mt][nt][2] * scale, acc[mt][nt][3] * scale);
            size_t r0 = (size_t)(row0 + mt * 16) * ldc + col0 + nt * 8;
            *reinterpret_cast<float2*>(Cz + r0)                   = v0;
            *reinterpret_cast<float2*>(Cz + r0 + 8 * (size_t)ldc) = v1;
        }
    }
}

// =================================================================================
// Elementwise kernels
// =================================================================================
__device__ __forceinline__ void sp(float v, bf16& h, bf16& l) {
    h = __float2bfloat16_rn(v);
    l = __float2bfloat16_rn(v - __bfloat162float(h));
}
__device__ __forceinline__ void sph(float v, __half& h, __half& l) {
    h = __float2half_rn(v);
    l = __float2half_rn(v - __half2float(h));
}

// float -> fp16 hi/lo
__global__ void splitf2_kernel(const float* __restrict__ in,
                               __half* __restrict__ hi, __half* __restrict__ lo, int n4)
{
    int i = blockIdx.x * 256 + threadIdx.x;
    if (i >= n4) return;
    float4 v = reinterpret_cast<const float4*>(in)[i];
    __half h0, l0, h1, l1, h2, l2, h3, l3;
    sph(v.x, h0, l0); sph(v.y, h1, l1); sph(v.z, h2, l2); sph(v.w, h3, l3);
    reinterpret_cast<__half2*>(hi)[i * 2]     = __halves2half2(h0, h1);
    reinterpret_cast<__half2*>(hi)[i * 2 + 1] = __halves2half2(h2, h3);
    reinterpret_cast<__half2*>(lo)[i * 2]     = __halves2half2(l0, l1);
    reinterpret_cast<__half2*>(lo)[i * 2 + 1] = __halves2half2(l2, l3);
}

// float -> fp16 single
__global__ void splitf1_kernel(const float* __restrict__ in,
                               __half* __restrict__ f, int n4)
{
    int i = blockIdx.x * 256 + threadIdx.x;
    if (i >= n4) return;
    float4 v = reinterpret_cast<const float4*>(in)[i];
    reinterpret_cast<__half2*>(f)[i * 2]     = __halves2half2(__float2half_rn(v.x), __float2half_rn(v.y));
    reinterpret_cast<__half2*>(f)[i * 2 + 1] = __halves2half2(__float2half_rn(v.z), __float2half_rn(v.w));
}

__global__ void bmean_kernel(const float* __restrict__ bias, float* __restrict__ bm)
{
    __shared__ float red[256];
    int r = blockIdx.x;
    const float* row = bias + (size_t)r * SQ;
    float s = 0.f;
    for (int i = threadIdx.x; i < SQ; i += 256) s += row[i];
    red[threadIdx.x] = s; __syncthreads();
    for (int o = 128; o; o >>= 1) {
        if (threadIdx.x < o) red[threadIdx.x] += red[threadIdx.x + o];
        __syncthreads();
    }
    if (threadIdx.x == 0) bm[r] = red[0] * (0.1f / 2048.0f);
}

__global__ void rope_split_kernel(const float* __restrict__ q, const float* __restrict__ k,
                                  const float* __restrict__ bm,
                                  bf16* __restrict__ qh, bf16* __restrict__ ql,
                                  bf16* __restrict__ kh, bf16* __restrict__ kl)
{
    __shared__ float sinvf[64];
    if (threadIdx.x < 64)
        sinvf[threadIdx.x] =
            (float)exp(-((double)(2 * threadIdx.x) / 128.0) * log(10000.0));
    __syncthreads();

    int idx = blockIdx.x * 256 + threadIdx.x;
    int d2 = idx & 63;
    int h  = (idx >> 6) & 15;
    int m  = idx >> 10;
    int s  = m & (SQ - 1);

    float sn, cs;
    sincosf((float)s * sinvf[d2], &sn, &cs);
    float b = bm[s];

    size_t off = (size_t)m * HID + (size_t)h * 128 + d2;
    float q0 = q[off], q1 = q[off + 64];
    float k0 = k[off], k1 = k[off + 64];
    float qa = q0 * cs - q1 * sn + b;
    float qb = q1 * cs + q0 * sn + b;
    float ka = k0 * cs - k1 * sn + b;
    float kb = k1 * cs + k0 * sn + b;
    bf16 h_, l_;
    sp(qa, h_, l_); qh[off]      = h_; ql[off]      = l_;
    sp(qb, h_, l_); qh[off + 64] = h_; ql[off + 64] = l_;
    sp(ka, h_, l_); kh[off]      = h_; kl[off]      = l_;
    sp(kb, h_, l_); kh[off + 64] = h_; kl[off + 64] = l_;
}

// v fp32 -> vT fp16 hi/lo [(b*16+h)*128+d][s]
__global__ void vsplit_kernel(const float* __restrict__ v,
                              __half* __restrict__ vth, __half* __restrict__ vtl)
{
    __shared__ float t[32][33];
    int z = blockIdx.z, b = z >> 4, h = z & 15;
    int s0 = blockIdx.x * 32, d0 = blockIdx.y * 32;
    int tx = threadIdx.x, ty = threadIdx.y;
#pragma unroll
    for (int i = 0; i < 4; i++) {
        int sl = ty * 4 + i;
        t[sl][tx] = v[(size_t)(b * SQ + s0 + sl) * HID + h * 128 + d0 + tx];
    }
    __syncthreads();
#pragma unroll
    for (int i = 0; i < 4; i++) {
        int dl = ty * 4 + i;
        float x = t[tx][dl];
        __half hi, lo; sph(x, hi, lo);
        size_t o = ((size_t)z * 128 + d0 + dl) * SQ + s0 + tx;
        vth[o] = hi; vtl[o] = lo;
    }
}

// causal softmax with bias; writes fp16 single attn for AV + fp32 (if output).
__global__ void softmax_kernel(float* __restrict__ attn, const float* __restrict__ bias,
                               __half* __restrict__ af, int writeAttn)
{
    __shared__ float buf[2048];
    __shared__ float red[256];
    int qrow = blockIdx.x;
    long long base = (long long)blockIdx.y * SQ * SQ + (long long)qrow * SQ;
    float* row = attn + base;
    const float* brow = bias + (size_t)qrow * SQ;
    int L  = qrow + 1;
    int L4 = L & ~3;
    int tileEnd = ((qrow >> 7) + 1) << 7;
    int tid = threadIdx.x;

    float mx = -3.402823466e38f;
    for (int i = tid * 4; i < L4; i += 1024) {
        float4 r = *reinterpret_cast<const float4*>(row + i);
        float4 bb = *reinterpret_cast<const float4*>(brow + i);
        r.x += bb.x; r.y += bb.y; r.z += bb.z; r.w += bb.w;
        *reinterpret_cast<float4*>(buf + i) = r;
        mx = fmaxf(mx, fmaxf(fmaxf(r.x, r.y), fmaxf(r.z, r.w)));
    }
    for (int i = L4 + tid; i < L; i += 256) {
        float vv = row[i] + brow[i];
        buf[i] = vv;
        mx = fmaxf(mx, vv);
    }
    red[tid] = mx; __syncthreads();
    for (int o = 128; o; o >>= 1) {
        if (tid < o) red[tid] = fmaxf(red[tid], red[tid + o]);
        __syncthreads();
    }
    mx = red[0]; __syncthreads();

    float sum = 0.f;
    for (int i = tid; i < L; i += 256) {
        float e = __expf(buf[i] - mx);
        buf[i] = e;
        sum += e;
    }
    red[tid] = sum; __syncthreads();
    for (int o = 128; o; o >>= 1) {
        if (tid < o) red[tid] += red[tid + o];
        __syncthreads();
    }
    float inv = 1.0f / red[0];
    __syncthreads();

    for (int i = tid * 4; i < L4; i += 1024) {
        float a0 = buf[i]     * inv;
        float a1 = buf[i + 1] * inv;
        float a2 = buf[i + 2] * inv;
        float a3 = buf[i + 3] * inv;
        *reinterpret_cast<__half2*>(af + base + i)     =
            __halves2half2(__float2half_rn(a0), __float2half_rn(a1));
        *reinterpret_cast<__half2*>(af + base + i + 2) =
            __halves2half2(__float2half_rn(a2), __float2half_rn(a3));
        if (writeAttn)
            *reinterpret_cast<float4*>(row + i) = make_float4(a0, a1, a2, a3);
    }
    for (int i = L4 + tid; i < L; i += 256) {
        float a = buf[i] * inv;
        af[base + i] = __float2half_rn(a);
        if (writeAttn) row[i] = a;
    }
    __half z16 = __float2half_rn(0.f);
    for (int i = L + tid; i < tileEnd; i += 256) af[base + i] = z16;
    if (writeAttn)
        for (int i = L + tid; i < SQ; i += 256) row[i] = 0.f;
}

// =================================================================================
// Host launcher
// =================================================================================
extern "C" void kernel_launch(void* const* d_in, const int* in_sizes, int n_in,
                              void* d_out, int out_size)
{
    const float* x    = (const float*)d_in[0];
    const float* Wq   = (const float*)d_in[1];
    const float* Wk   = (const float*)d_in[2];
    const float* Wv   = (const float*)d_in[3];
    const float* Wo   = (const float*)d_in[4];
    const float* bias = (const float*)d_in[5];
    float* out = (float*)d_out;

    float *pqkv, *pao, *pbm, *pattn;
    bf16 *pqh, *pql, *pkh, *pkl;
    __half *pxf, *pwfh, *pwfl, *paf, *pvth, *pvtl, *paof, *pwofh, *pwofl;
    cudaGetSymbolAddress((void**)&pqkv, g_qkv); cudaGetSymbolAddress((void**)&pao, g_ao);
    cudaGetSymbolAddress((void**)&pbm, g_bm);   cudaGetSymbolAddress((void**)&pattn, g_attn);
    cudaGetSymbolAddress((void**)&pqh, g_qh);   cudaGetSymbolAddress((void**)&pql, g_ql);
    cudaGetSymbolAddress((void**)&pkh, g_kh);   cudaGetSymbolAddress((void**)&pkl, g_kl);
    cudaGetSymbolAddress((void**)&pxf, g_xf);
    cudaGetSymbolAddress((void**)&pwfh, g_wfh); cudaGetSymbolAddress((void**)&pwfl, g_wfl);
    cudaGetSymbolAddress((void**)&paf, g_af);
    cudaGetSymbolAddress((void**)&pvth, g_vth); cudaGetSymbolAddress((void**)&pvtl, g_vtl);
    cudaGetSymbolAddress((void**)&paof, g_aof);
    cudaGetSymbolAddress((void**)&pwofh, g_wofh); cudaGetSymbolAddress((void**)&pwofl, g_wofl);

    const long long OUT_N = 8388608LL, ATT_N = 134217728LL;
    float* outPtr = out;
    float* attnPtr;
    int writeAttn = 1;
    long long osz = (long long)out_size;
    if (osz >= OUT_N + ATT_N) { attnPtr = out + OUT_N; }
    else if (osz == ATT_N)    { attnPtr = out; outPtr = pqkv; }
    else                      { attnPtr = pattn; writeAttn = 0; }

    const long long SH = (long long)SQ * HID;
    const long long SS = (long long)SQ * SQ;
    const long long WW = (long long)HID * HID;
    const long long QKVS = (long long)MR * HID;
    const int SMEM  = 3 * 40960;
    const int SMEM2 = 3 * 30720;
    cudaFuncSetAttribute(mma_gemm,  cudaFuncAttributeMaxDynamicSharedMemorySize, SMEM);
    cudaFuncSetAttribute(mma_gemm2, cudaFuncAttributeMaxDynamicSharedMemorySize, SMEM2);

    splitf1_kernel<<<8192, 256>>>(x, pxf, 2097152);
    splitf2_kernel<<<4096, 256>>>(Wq, pwfh,        pwfl,        1048576);
    splitf2_kernel<<<4096, 256>>>(Wk, pwfh + WW,   pwfl + WW,   1048576);
    splitf2_kernel<<<4096, 256>>>(Wv, pwfh + 2*WW, pwfl + 2*WW, 1048576);
    splitf2_kernel<<<4096, 256>>>(Wo, pwofh, pwofl, 1048576);

    // merged QKV projection : 2-pass fp16 (x single, W hi/lo)
    dim3 gQKV(16, 32, 3);
    mma_gemm2<<<gQKV, 256, SMEM2>>>(pxf, pwfh, pwfl, pqkv, 2048, 2048, 2048, 2048,
                                    0, 0, WW, 0, QKVS, 0, 1, 1.0f, 0);

    bmean_kernel<<<SQ, 256>>>(bias, pbm);

    float* pq = pqkv;
    float* pk = pqkv + QKVS;
    float* pv = pqkv + 2 * QKVS;
    rope_split_kernel<<<16384, 256>>>(pq, pk, pbm, pqh, pql, pkh, pkl);
    vsplit_kernel<<<dim3(64, 4, 32), dim3(32, 8)>>>(pv, pvth, pvtl);

    // scores = q.k^T / sqrt(128) : 3-pass bf16 (accurate attn path), causal tile-skip
    dim3 gScore(16, 16, 32);
    mma_gemm<<<gScore, 256, SMEM>>>(pqh, pql, pkh, pkl, attnPtr, 128, 2048, 2048, 2048,
                                    SH, 128, SH, 128,
                                    16 * SS, SS, 16, 0.08838834764831845f, 1);

    softmax_kernel<<<dim3(SQ, 32), 256>>>(attnPtr, bias, paf, writeAttn);

    // attn @ v : 2-pass fp16, K-limited, heavy-first
    dim3 gAV(1, 16, 32);
    mma_gemm2<<<gAV, 256, SMEM2>>>(paf, pvth, pvtl, pao, 2048, 2048, 2048, 2048,
                                   16 * SS, SS, SH, (long long)128 * SQ,
                                   SH, 128, 16, 1.0f, 6);

    splitf1_kernel<<<8192, 256>>>(pao, paof, 2097152);

    // output = attn_out @ Wo^T : 2-pass fp16
    dim3 gProj(16, 32, 1);
    mma_gemm2<<<gProj, 256, SMEM2>>>(paof, pwofh, pwofl, outPtr, 2048, 2048, 2048, 2048,
                                     0, 0, 0, 0, 0, 0, 1, 1.0f, 0);
}

// round 15
// speedup vs baseline: 1.4508x; 1.1012x over previous
#include <cuda_runtime.h>
#include <cuda_bf16.h>
#include <cuda_fp16.h>
#include <math.h>
#include <stdint.h>

#define SQ   2048
#define HID  2048
#define MR   4096

typedef __nv_bfloat16  bf16;
typedef __nv_bfloat162 bf162;

// ----------------------------- static scratch ------------------------------
__device__ float g_qkv[3u * MR * HID];
__device__ float g_bm [SQ];
__device__ float g_attn[134217728];

__device__ bf16 g_qh [MR * HID],  g_ql [MR * HID];
__device__ bf16 g_kh [MR * HID],  g_kl [MR * HID];

__device__ __half g_xf  [MR * HID];                    // x fp16 (single)
__device__ __half g_wfh [3u * HID * HID];              // Wq,Wk,Wv fp16 hi
__device__ __half g_wfl [3u * HID * HID];              // Wq,Wk,Wv fp16 lo
__device__ __half g_af  [134217728];                   // attn fp16 (single)
__device__ __half g_vtf [MR * HID];                    // vT fp16 (single)
__device__ __half g_aof [MR * HID];                    // ao fp16 (single)
__device__ __half g_wof [HID * HID];                   // Wo fp16 (single)

// ----------------------------- helpers -------------------------------------
__device__ __forceinline__ uint32_t smem_u32(const void* p) {
    uint32_t a;
    asm("{ .reg .u64 t; cvta.to.shared.u64 t, %1; cvt.u32.u64 %0, t; }" : "=r"(a) : "l"(p));
    return a;
}
__device__ __forceinline__ void cp16(uint32_t dst, const void* src) {
    asm volatile("cp.async.cg.shared.global [%0], [%1], 16;" :: "r"(dst), "l"(src));
}
#define CP_COMMIT() asm volatile("cp.async.commit_group;" ::: "memory")
#define CP_WAIT(n)  asm volatile("cp.async.wait_group %0;" :: "n"(n) : "memory")

#define LDSM4(r0, r1, r2, r3, addr) \
    asm volatile("ldmatrix.sync.aligned.m8n8.x4.shared.b16 {%0,%1,%2,%3}, [%4];" \
        : "=r"(r0), "=r"(r1), "=r"(r2), "=r"(r3) : "r"(addr))

__device__ __forceinline__ void mma_bf16(float* c,
    uint32_t a0, uint32_t a1, uint32_t a2, uint32_t a3, uint32_t b0, uint32_t b1)
{
    asm volatile(
        "mma.sync.aligned.m16n8k16.row.col.f32.bf16.bf16.f32 "
        "{%0,%1,%2,%3}, {%4,%5,%6,%7}, {%8,%9}, {%0,%1,%2,%3};"
        : "+f"(c[0]), "+f"(c[1]), "+f"(c[2]), "+f"(c[3])
        : "r"(a0), "r"(a1), "r"(a2), "r"(a3), "r"(b0), "r"(b1));
}
__device__ __forceinline__ void mma_f16(float* c,
    uint32_t a0, uint32_t a1, uint32_t a2, uint32_t a3, uint32_t b0, uint32_t b1)
{
    asm volatile(
        "mma.sync.aligned.m16n8k16.row.col.f32.f16.f16.f32 "
        "{%0,%1,%2,%3}, {%4,%5,%6,%7}, {%8,%9}, {%0,%1,%2,%3};"
        : "+f"(c[0]), "+f"(c[1]), "+f"(c[2]), "+f"(c[3])
        : "r"(a0), "r"(a1), "r"(a2), "r"(a3), "r"(b0), "r"(b1));
}

// =================================================================================
// 3-pass split-bf16 NT GEMM (exact path): scores only.
// =================================================================================
#define STG_BYTES 40960u
#define ARR_BYTES 10240u

__device__ __forceinline__ void load_stage32(
    uint32_t sbase, int slot, int k0,
    const bf16* __restrict__ Ah, const bf16* __restrict__ Al,
    const bf16* __restrict__ Bh, const bf16* __restrict__ Bl,
    int lda, int ldb, int rowBase, int colBase, int tid)
{
    uint32_t base = sbase + (uint32_t)slot * STG_BYTES;
    int r  = tid >> 1;
    int c0 = (tid & 1) << 1;
#pragma unroll
    for (int i = 0; i < 2; i++) {
        int c = c0 + i;
        uint32_t off = (uint32_t)(r * 40 + c * 8) * 2;
        const size_t ga = (size_t)(rowBase + r) * lda + k0 + c * 8;
        const size_t gb = (size_t)(colBase + r) * ldb + k0 + c * 8;
        cp16(base +                off, Ah + ga);
        cp16(base + ARR_BYTES    + off, Al + ga);
        cp16(base + 2u*ARR_BYTES + off, Bh + gb);
        cp16(base + 3u*ARR_BYTES + off, Bl + gb);
    }
    CP_COMMIT();
}

__global__ void __launch_bounds__(256, 1)
mma_gemm(const bf16* __restrict__ Ahi, const bf16* __restrict__ Alo,
         const bf16* __restrict__ Bhi, const bf16* __restrict__ Blo,
         float* __restrict__ C,
         int K, int lda, int ldb, int ldc,
         long long aSb, long long aSh, long long bSb, long long bSh,
         long long cSb, long long cSh, int nInner, float scale, int mode)
{
    extern __shared__ char smem[];
    const int z  = blockIdx.z;
    const int bb = z / nInner, hh = z - bb * nInner;
    const bf16* Ah = Ahi + bb * aSb + hh * aSh;
    const bf16* Al = Alo + bb * aSb + hh * aSh;
    const bf16* Bh = Bhi + bb * bSb + hh * bSh;
    const bf16* Bl = Blo + bb * bSb + hh * bSh;
    float* Cz = C + bb * cSb + hh * cSh;

    const int yIdx = (mode & 4) ? (gridDim.y - 1 - blockIdx.y) : blockIdx.y;
    const int rowBase = yIdx * 128;
    const int colBase = blockIdx.x * 128;
    if ((mode & 1) && colBase > rowBase + 127) return;
    int Keff = K;
    if (mode & 2) { int kl = rowBase + 128; Keff = kl < K ? kl : K; }
    const int nst = Keff >> 5;

    const uint32_t sb = smem_u32(smem);
    const int tid = threadIdx.x, lane = tid & 31, wid = tid >> 5;
    const int warpM = (wid & 1) << 6;
    const int warpN = (wid >> 1) << 5;

    const uint32_t offA = (uint32_t)((warpM + (lane & 15)) * 40
                                     + ((lane >> 4) << 3)) * 2;
    const uint32_t offB = (uint32_t)((warpN + (lane & 7) + ((lane >> 4) << 3)) * 40
                                     + (((lane >> 3) & 1) << 3)) * 2;

    float acc[4][4][4];
#pragma unroll
    for (int i = 0; i < 4; i++)
#pragma unroll
        for (int j = 0; j < 4; j++)
#pragma unroll
            for (int t = 0; t < 4; t++) acc[i][j][t] = 0.f;

    load_stage32(sb, 0, 0, Ah, Al, Bh, Bl, lda, ldb, rowBase, colBase, tid);
    if (nst > 1)
        load_stage32(sb, 1, 32, Ah, Al, Bh, Bl, lda, ldb, rowBase, colBase, tid);

    int slot = 0;
    for (int j = 0; j < nst; j++) {
        if (j + 2 < nst) {
            int ns = slot + 2; if (ns >= 3) ns -= 3;
            load_stage32(sb, ns, (j + 2) * 32, Ah, Al, Bh, Bl,
                         lda, ldb, rowBase, colBase, tid);
            CP_WAIT(2);
        } else if (j + 1 < nst) {
            CP_WAIT(1);
        } else {
            CP_WAIT(0);
        }
        __syncthreads();

        const uint32_t base = sb + (uint32_t)slot * STG_BYTES;
#pragma unroll
        for (int ks = 0; ks < 32; ks += 16) {
            uint32_t ah[4][4], al[4][4], bh[2][4], bl[2][4];
#pragma unroll
            for (int t = 0; t < 4; t++) {
                uint32_t ad = base + offA + (uint32_t)((t * 640 + ks) * 2);
                LDSM4(ah[t][0], ah[t][1], ah[t][2], ah[t][3], ad);
                LDSM4(al[t][0], al[t][1], al[t][2], al[t][3], ad + ARR_BYTES);
            }
#pragma unroll
            for (int g = 0; g < 2; g++) {
                uint32_t bd = base + 2u*ARR_BYTES + offB + (uint32_t)((g * 640 + ks) * 2);
                LDSM4(bh[g][0], bh[g][1], bh[g][2], bh[g][3], bd);
                LDSM4(bl[g][0], bl[g][1], bl[g][2], bl[g][3], bd + ARR_BYTES);
            }
#pragma unroll
            for (int mt = 0; mt < 4; mt++) {
#pragma unroll
                for (int g = 0; g < 2; g++) {
                    mma_bf16(acc[mt][2*g],   ah[mt][0], ah[mt][1], ah[mt][2], ah[mt][3], bh[g][0], bh[g][1]);
                    mma_bf16(acc[mt][2*g+1], ah[mt][0], ah[mt][1], ah[mt][2], ah[mt][3], bh[g][2], bh[g][3]);
                    mma_bf16(acc[mt][2*g],   ah[mt][0], ah[mt][1], ah[mt][2], ah[mt][3], bl[g][0], bl[g][1]);
                    mma_bf16(acc[mt][2*g+1], ah[mt][0], ah[mt][1], ah[mt][2], ah[mt][3], bl[g][2], bl[g][3]);
                    mma_bf16(acc[mt][2*g],   al[mt][0], al[mt][1], al[mt][2], al[mt][3], bh[g][0], bh[g][1]);
                    mma_bf16(acc[mt][2*g+1], al[mt][0], al[mt][1], al[mt][2], al[mt][3], bh[g][2], bh[g][3]);
                }
            }
        }
        __syncthreads();
        if (++slot >= 3) slot = 0;
    }

    const int row0 = rowBase + warpM + (lane >> 2);
    const int col0 = colBase + warpN + (lane & 3) * 2;
#pragma unroll
    for (int mt = 0; mt < 4; mt++) {
#pragma unroll
        for (int nt = 0; nt < 4; nt++) {
            float2 v0 = make_float2(acc[mt][nt][0] * scale, acc[mt][nt][1] * scale);
            float2 v1 = make_float2(acc[mt][nt][2] * scale, acc[mt][nt][3] * scale);
            size_t r0 = (size_t)(row0 + mt * 16) * ldc + col0 + nt * 8;
            *reinterpret_cast<float2*>(Cz + r0)                   = v0;
            *reinterpret_cast<float2*>(Cz + r0 + 8 * (size_t)ldc) = v1;
        }
    }
}

// =================================================================================
// 2-pass fp16 NT GEMM: C = scale * Af * (Bh + Bl)^T.  (QKV projection)
// =================================================================================
#define ARR2 10240u
#define STG2 30720u

__device__ __forceinline__ void load_stage32f(
    uint32_t sbase, int slot, int k0,
    const __half* __restrict__ Af,
    const __half* __restrict__ Bh, const __half* __restrict__ Bl,
    int lda, int ldb, int rowBase, int colBase, int tid)
{
    uint32_t base = sbase + (uint32_t)slot * STG2;
    int r  = tid >> 1;
    int c0 = (tid & 1) << 1;
#pragma unroll
    for (int i = 0; i < 2; i++) {
        int c = c0 + i;
        uint32_t off = (uint32_t)(r * 40 + c * 8) * 2;
        const size_t ga = (size_t)(rowBase + r) * lda + k0 + c * 8;
        const size_t gb = (size_t)(colBase + r) * ldb + k0 + c * 8;
        cp16(base +           off, Af + ga);
        cp16(base + ARR2    + off, Bh + gb);
        cp16(base + 2u*ARR2 + off, Bl + gb);
    }
    CP_COMMIT();
}

__global__ void __launch_bounds__(256, 1)
mma_gemm2(const __half* __restrict__ Afi,
          const __half* __restrict__ Bhi, const __half* __restrict__ Bli,
          float* __restrict__ C,
          int K, int lda, int ldb, int ldc,
          long long aSb, long long aSh, long long bSb, long long bSh,
          long long cSb, long long cSh, int nInner, float scale, int mode)
{
    extern __shared__ char smem[];
    const int z  = blockIdx.z;
    const int bb = z / nInner, hh = z - bb * nInner;
    const __half* Af = Afi + bb * aSb + hh * aSh;
    const __half* Bh = Bhi + bb * bSb + hh * bSh;
    const __half* Bl = Bli + bb * bSb + hh * bSh;
    float* Cz = C + bb * cSb + hh * cSh;

    const int yIdx = (mode & 4) ? (gridDim.y - 1 - blockIdx.y) : blockIdx.y;
    const int rowBase = yIdx * 128;
    const int colBase = blockIdx.x * 128;
    if ((mode & 1) && colBase > rowBase + 127) return;
    int Keff = K;
    if (mode & 2) { int kl = rowBase + 128; Keff = kl < K ? kl : K; }
    const int nst = Keff >> 5;

    const uint32_t sb = smem_u32(smem);
    const int tid = threadIdx.x, lane = tid & 31, wid = tid >> 5;
    const int warpM = (wid & 1) << 6;
    const int warpN = (wid >> 1) << 5;

    const uint32_t offA = (uint32_t)((warpM + (lane & 15)) * 40
                                     + ((lane >> 4) << 3)) * 2;
    const uint32_t offB = (uint32_t)((warpN + (lane & 7) + ((lane >> 4) << 3)) * 40
                                     + (((lane >> 3) & 1) << 3)) * 2;

    float acc[4][4][4];
#pragma unroll
    for (int i = 0; i < 4; i++)
#pragma unroll
        for (int j = 0; j < 4; j++)
#pragma unroll
            for (int t = 0; t < 4; t++) acc[i][j][t] = 0.f;

    load_stage32f(sb, 0, 0, Af, Bh, Bl, lda, ldb, rowBase, colBase, tid);
    if (nst > 1)
        load_stage32f(sb, 1, 32, Af, Bh, Bl, lda, ldb, rowBase, colBase, tid);

    int slot = 0;
    for (int j = 0; j < nst; j++) {
        if (j + 2 < nst) {
            int ns = slot + 2; if (ns >= 3) ns -= 3;
            load_stage32f(sb, ns, (j + 2) * 32, Af, Bh, Bl,
                          lda, ldb, rowBase, colBase, tid);
            CP_WAIT(2);
        } else if (j + 1 < nst) {
            CP_WAIT(1);
        } else {
            CP_WAIT(0);
        }
        __syncthreads();

        const uint32_t base = sb + (uint32_t)slot * STG2;
#pragma unroll
        for (int ks = 0; ks < 32; ks += 16) {
            uint32_t af[4][4], bh[2][4], bl[2][4];
#pragma unroll
            for (int t = 0; t < 4; t++) {
                uint32_t ad = base + offA + (uint32_t)((t * 640 + ks) * 2);
                LDSM4(af[t][0], af[t][1], af[t][2], af[t][3], ad);
            }
#pragma unroll
            for (int g = 0; g < 2; g++) {
                uint32_t bd = base + ARR2 + offB + (uint32_t)((g * 640 + ks) * 2);
                LDSM4(bh[g][0], bh[g][1], bh[g][2], bh[g][3], bd);
                LDSM4(bl[g][0], bl[g][1], bl[g][2], bl[g][3], bd + ARR2);
            }
#pragma unroll
            for (int mt = 0; mt < 4; mt++) {
#pragma unroll
                for (int g = 0; g < 2; g++) {
                    mma_f16(acc[mt][2*g],   af[mt][0], af[mt][1], af[mt][2], af[mt][3], bh[g][0], bh[g][1]);
                    mma_f16(acc[mt][2*g+1], af[mt][0], af[mt][1], af[mt][2], af[mt][3], bh[g][2], bh[g][3]);
                    mma_f16(acc[mt][2*g],   af[mt][0], af[mt][1], af[mt][2], af[mt][3], bl[g][0], bl[g][1]);
                    mma_f16(acc[mt][2*g+1], af[mt][0], af[mt][1], af[mt][2], af[mt][3], bl[g][2], bl[g][3]);
                }
            }
        }
        __syncthreads();
        if (++slot >= 3) slot = 0;
    }

    const int row0 = rowBase + warpM + (lane >> 2);
    const int col0 = colBase + warpN + (lane & 3) * 2;
#pragma unroll
    for (int mt = 0; mt < 4; mt++) {
#pragma unroll
        for (int nt = 0; nt < 4; nt++) {
            float2 v0 = make_float2(acc[mt][nt][0] * scale, acc[mt][nt][1] * scale);
            float2 v1 = make_float2(acc[mt][nt][2] * scale, acc[mt][nt][3] * scale);
            size_t r0 = (size_t)(row0 + mt * 16) * ldc + col0 + nt * 8;
            *reinterpret_cast<float2*>(Cz + r0)                   = v0;
            *reinterpret_cast<float2*>(Cz + r0 + 8 * (size_t)ldc) = v1;
        }
    }
}

// =================================================================================
// 1-pass fp16 NT GEMM: C = scale * Af * Bf^T. Float OR half output.
// Used for attn@v (half out -> ao fp16 directly) and out-proj (float out).
// =================================================================================
#define STG1 20480u

__device__ __forceinline__ void load_stage32g(
    uint32_t sbase, int slot, int k0,
    const __half* __restrict__ Af, const __half* __restrict__ Bf,
    int lda, int ldb, int rowBase, int colBase, int tid)
{
    uint32_t base = sbase + (uint32_t)slot * STG1;
    int r  = tid >> 1;
    int c0 = (tid & 1) << 1;
#pragma unroll
    for (int i = 0; i < 2; i++) {
        int c = c0 + i;
        uint32_t off = (uint32_t)(r * 40 + c * 8) * 2;
        cp16(base +        off, Af + (size_t)(rowBase + r) * lda + k0 + c * 8);
        cp16(base + ARR2 + off, Bf + (size_t)(colBase + r) * ldb + k0 + c * 8);
    }
    CP_COMMIT();
}

__global__ void __launch_bounds__(256, 1)
mma_gemm1(const __half* __restrict__ Afi, const __half* __restrict__ Bfi,
          float* __restrict__ Cf, __half* __restrict__ Ch,
          int K, int lda, int ldb, int ldc,
          long long aSb, long long aSh, long long bSb, long long bSh,
          long long cSb, long long cSh, int nInner, float scale, int mode)
{
    extern __shared__ char smem[];
    const int z  = blockIdx.z;
    const int bb = z / nInner, hh = z - bb * nInner;
    const __half* Af = Afi + bb * aSb + hh * aSh;
    const __half* Bf = Bfi + bb * bSb + hh * bSh;

    const int yIdx = (mode & 4) ? (gridDim.y - 1 - blockIdx.y) : blockIdx.y;
    const int rowBase = yIdx * 128;
    const int colBase = blockIdx.x * 128;
    if ((mode & 1) && colBase > rowBase + 127) return;
    int Keff = K;
    if (mode & 2) { int kl = rowBase + 128; Keff = kl < K ? kl : K; }
    const int nst = Keff >> 5;

    const uint32_t sb = smem_u32(smem);
    const int tid = threadIdx.x, lane = tid & 31, wid = tid >> 5;
    const int warpM = (wid & 1) << 6;
    const int warpN = (wid >> 1) << 5;

    const uint32_t offA = (uint32_t)((warpM + (lane & 15)) * 40
                                     + ((lane >> 4) << 3)) * 2;
    const uint32_t offB = (uint32_t)((warpN + (lane & 7) + ((lane >> 4) << 3)) * 40
                                     + (((lane >> 3) & 1) << 3)) * 2;

    float acc[4][4][4];
#pragma unroll
    for (int i = 0; i < 4; i++)
#pragma unroll
        for (int j = 0; j < 4; j++)
#pragma unroll
            for (int t = 0; t < 4; t++) acc[i][j][t] = 0.f;

    load_stage32g(sb, 0, 0, Af, Bf, lda, ldb, rowBase, colBase, tid);
    if (nst > 1)
        load_stage32g(sb, 1, 32, Af, Bf, lda, ldb, rowBase, colBase, tid);

    int slot = 0;
    for (int j = 0; j < nst; j++) {
        if (j + 2 < nst) {
            int ns = slot + 2; if (ns >= 3) ns -= 3;
            load_stage32g(sb, ns, (j + 2) * 32, Af, Bf,
                          lda, ldb, rowBase, colBase, tid);
            CP_WAIT(2);
        } else if (j + 1 < nst) {
            CP_WAIT(1);
        } else {
            CP_WAIT(0);
        }
        __syncthreads();

        const uint32_t base = sb + (uint32_t)slot * STG1;
#pragma unroll
        for (int ks = 0; ks < 32; ks += 16) {
            uint32_t af[4][4], bf[2][4];
#pragma unroll
            for (int t = 0; t < 4; t++) {
                uint32_t ad = base + offA + (uint32_t)((t * 640 + ks) * 2);
                LDSM4(af[t][0], af[t][1], af[t][2], af[t][3], ad);
            }
#pragma unroll
            for (int g = 0; g < 2; g++) {
                uint32_t bd = base + ARR2 + offB + (uint32_t)((g * 640 + ks) * 2);
                LDSM4(bf[g][0], bf[g][1], bf[g][2], bf[g][3], bd);
            }
#pragma unroll
            for (int mt = 0; mt < 4; mt++) {
#pragma unroll
                for (int g = 0; g < 2; g++) {
                    mma_f16(acc[mt][2*g],   af[mt][0], af[mt][1], af[mt][2], af[mt][3], bf[g][0], bf[g][1]);
                    mma_f16(acc[mt][2*g+1], af[mt][0], af[mt][1], af[mt][2], af[mt][3], bf[g][2], bf[g][3]);
                }
            }
        }
        __syncthreads();
        if (++slot >= 3) slot = 0;
    }

    const int row0 = rowBase + warpM + (lane >> 2);
    const int col0 = colBase + warpN + (lane & 3) * 2;
    if (Ch) {
        __half* Cz = Ch + bb * cSb + hh * cSh;
#pragma unroll
        for (int mt = 0; mt < 4; mt++) {
#pragma unroll
            for (int nt = 0; nt < 4; nt++) {
                size_t r0 = (size_t)(row0 + mt * 16) * ldc + col0 + nt * 8;
                *reinterpret_cast<__half2*>(Cz + r0) =
                    __halves2half2(__float2half_rn(acc[mt][nt][0] * scale),
                                   __float2half_rn(acc[mt][nt][1] * scale));
                *reinterpret_cast<__half2*>(Cz + r0 + 8 * (size_t)ldc) =
                    __halves2half2(__float2half_rn(acc[mt][nt][2] * scale),
                                   __float2half_rn(acc[mt][nt][3] * scale));
            }
        }
    } else {
        float* Cz = Cf + bb * cSb + hh * cSh;
#pragma unroll
        for (int mt = 0; mt < 4; mt++) {
#pragma unroll
            for (int nt = 0; nt < 4; nt++) {
                float2 v0 = make_float2(acc[mt][nt][0] * scale, acc[mt][nt][1] * scale);
                float2 v1 = make_float2(acc[mt][nt][2] * scale, acc[mt][nt][3] * scale);
                size_t r0 = (size_t)(row0 + mt * 16) * ldc + col0 + nt * 8;
                *reinterpret_cast<float2*>(Cz + r0)                   = v0;
                *reinterpret_cast<float2*>(Cz + r0 + 8 * (size_t)ldc) = v1;
            }
        }
    }
}

// =================================================================================
// Elementwise kernels
// =================================================================================
__device__ __forceinline__ void sp(float v, bf16& h, bf16& l) {
    h = __float2bfloat16_rn(v);
    l = __float2bfloat16_rn(v - __bfloat162float(h));
}
__device__ __forceinline__ void sph(float v, __half& h, __half& l) {
    h = __float2half_rn(v);
    l = __float2half_rn(v - __half2float(h));
}

__global__ void splitf2_kernel(const float* __restrict__ in,
                               __half* __restrict__ hi, __half* __restrict__ lo, int n4)
{
    int i = blockIdx.x * 256 + threadIdx.x;
    if (i >= n4) return;
    float4 v = reinterpret_cast<const float4*>(in)[i];
    __half h0, l0, h1, l1, h2, l2, h3, l3;
    sph(v.x, h0, l0); sph(v.y, h1, l1); sph(v.z, h2, l2); sph(v.w, h3, l3);
    reinterpret_cast<__half2*>(hi)[i * 2]     = __halves2half2(h0, h1);
    reinterpret_cast<__half2*>(hi)[i * 2 + 1] = __halves2half2(h2, h3);
    reinterpret_cast<__half2*>(lo)[i * 2]     = __halves2half2(l0, l1);
    reinterpret_cast<__half2*>(lo)[i * 2 + 1] = __halves2half2(l2, l3);
}

__global__ void splitf1_kernel(const float* __restrict__ in,
                               __half* __restrict__ f, int n4)
{
    int i = blockIdx.x * 256 + threadIdx.x;
    if (i >= n4) return;
    float4 v = reinterpret_cast<const float4*>(in)[i];
    reinterpret_cast<__half2*>(f)[i * 2]     = __halves2half2(__float2half_rn(v.x), __float2half_rn(v.y));
    reinterpret_cast<__half2*>(f)[i * 2 + 1] = __halves2half2(__float2half_rn(v.z), __float2half_rn(v.w));
}

__global__ void bmean_kernel(const float* __restrict__ bias, float* __restrict__ bm)
{
    __shared__ float red[256];
    int r = blockIdx.x;
    const float* row = bias + (size_t)r * SQ;
    float s = 0.f;
    for (int i = threadIdx.x; i < SQ; i += 256) s += row[i];
    red[threadIdx.x] = s; __syncthreads();
    for (int o = 128; o; o >>= 1) {
        if (threadIdx.x < o) red[threadIdx.x] += red[threadIdx.x + o];
        __syncthreads();
    }
    if (threadIdx.x == 0) bm[r] = red[0] * (0.1f / 2048.0f);
}

__global__ void rope_split_kernel(const float* __restrict__ q, const float* __restrict__ k,
                                  const float* __restrict__ bm,
                                  bf16* __restrict__ qh, bf16* __restrict__ ql,
                                  bf16* __restrict__ kh, bf16* __restrict__ kl)
{
    __shared__ float sinvf[64];
    if (threadIdx.x < 64)
        sinvf[threadIdx.x] =
            (float)exp(-((double)(2 * threadIdx.x) / 128.0) * log(10000.0));
    __syncthreads();

    int idx = blockIdx.x * 256 + threadIdx.x;
    int d2 = idx & 63;
    int h  = (idx >> 6) & 15;
    int m  = idx >> 10;
    int s  = m & (SQ - 1);

    float sn, cs;
    sincosf((float)s * sinvf[d2], &sn, &cs);
    float b = bm[s];

    size_t off = (size_t)m * HID + (size_t)h * 128 + d2;
    float q0 = q[off], q1 = q[off + 64];
    float k0 = k[off], k1 = k[off + 64];
    float qa = q0 * cs - q1 * sn + b;
    float qb = q1 * cs + q0 * sn + b;
    float ka = k0 * cs - k1 * sn + b;
    float kb = k1 * cs + k0 * sn + b;
    bf16 h_, l_;
    sp(qa, h_, l_); qh[off]      = h_; ql[off]      = l_;
    sp(qb, h_, l_); qh[off + 64] = h_; ql[off + 64] = l_;
    sp(ka, h_, l_); kh[off]      = h_; kl[off]      = l_;
    sp(kb, h_, l_); kh[off + 64] = h_; kl[off + 64] = l_;
}

// v fp32 -> vT fp16 single [(b*16+h)*128+d][s]
__global__ void vsplit_kernel(const float* __restrict__ v, __half* __restrict__ vtf)
{
    __shared__ float t[32][33];
    int z = blockIdx.z, b = z >> 4, h = z & 15;
    int s0 = blockIdx.x * 32, d0 = blockIdx.y * 32;
    int tx = threadIdx.x, ty = threadIdx.y;
#pragma unroll
    for (int i = 0; i < 4; i++) {
        int sl = ty * 4 + i;
        t[sl][tx] = v[(size_t)(b * SQ + s0 + sl) * HID + h * 128 + d0 + tx];
    }
    __syncthreads();
#pragma unroll
    for (int i = 0; i < 4; i++) {
        int dl = ty * 4 + i;
        size_t o = ((size_t)z * 128 + d0 + dl) * SQ + s0 + tx;
        vtf[o] = __float2half_rn(t[tx][dl]);
    }
}

// causal softmax with bias; writes fp16 single attn + fp32 (if output).
__global__ void softmax_kernel(float* __restrict__ attn, const float* __restrict__ bias,
                               __half* __restrict__ af, int writeAttn)
{
    __shared__ float buf[2048];
    __shared__ float red[256];
    int qrow = blockIdx.x;
    long long base = (long long)blockIdx.y * SQ * SQ + (long long)qrow * SQ;
    float* row = attn + base;
    const float* brow = bias + (size_t)qrow * SQ;
    int L  = qrow + 1;
    int L4 = L & ~3;
    int tileEnd = ((qrow >> 7) + 1) << 7;
    int tid = threadIdx.x;

    float mx = -3.402823466e38f;
    for (int i = tid * 4; i < L4; i += 1024) {
        float4 r = *reinterpret_cast<const float4*>(row + i);
        float4 bb = *reinterpret_cast<const float4*>(brow + i);
        r.x += bb.x; r.y += bb.y; r.z += bb.z; r.w += bb.w;
        *reinterpret_cast<float4*>(buf + i) = r;
        mx = fmaxf(mx, fmaxf(fmaxf(r.x, r.y), fmaxf(r.z, r.w)));
    }
    for (int i = L4 + tid; i < L; i += 256) {
        float vv = row[i] + brow[i];
        buf[i] = vv;
        mx = fmaxf(mx, vv);
    }
    red[tid] = mx; __syncthreads();
    for (int o = 128; o; o >>= 1) {
        if (tid < o) red[tid] = fmaxf(red[tid], red[tid + o]);
        __syncthreads();
    }
    mx = red[0]; __syncthreads();

    float sum = 0.f;
    for (int i = tid; i < L; i += 256) {
        float e = __expf(buf[i] - mx);
        buf[i] = e;
        sum += e;
    }
    red[tid] = sum; __syncthreads();
    for (int o = 128; o; o >>= 1) {
        if (tid < o) red[tid] += red[tid + o];
        __syncthreads();
    }
    float inv = 1.0f / red[0];
    __syncthreads();

    for (int i = tid * 4; i < L4; i += 1024) {
        float a0 = buf[i]     * inv;
        float a1 = buf[i + 1] * inv;
        float a2 = buf[i + 2] * inv;
        float a3 = buf[i + 3] * inv;
        *reinterpret_cast<__half2*>(af + base + i)     =
            __halves2half2(__float2half_rn(a0), __float2half_rn(a1));
        *reinterpret_cast<__half2*>(af + base + i + 2) =
            __halves2half2(__float2half_rn(a2), __float2half_rn(a3));
        if (writeAttn)
            *reinterpret_cast<float4*>(row + i) = make_float4(a0, a1, a2, a3);
    }
    for (int i = L4 + tid; i < L; i += 256) {
        float a = buf[i] * inv;
        af[base + i] = __float2half_rn(a);
        if (writeAttn) row[i] = a;
    }
    __half z16 = __float2half_rn(0.f);
    for (int i = L + tid; i < tileEnd; i += 256) af[base + i] = z16;
    if (writeAttn)
        for (int i = L + tid; i < SQ; i += 256) row[i] = 0.f;
}

// =================================================================================
// Host launcher
// =================================================================================
extern "C" void kernel_launch(void* const* d_in, const int* in_sizes, int n_in,
                              void* d_out, int out_size)
{
    const float* x    = (const float*)d_in[0];
    const float* Wq   = (const float*)d_in[1];
    const float* Wk   = (const float*)d_in[2];
    const float* Wv   = (const float*)d_in[3];
    const float* Wo   = (const float*)d_in[4];
    const float* bias = (const float*)d_in[5];
    float* out = (float*)d_out;

    float *pqkv, *pbm, *pattn;
    bf16 *pqh, *pql, *pkh, *pkl;
    __half *pxf, *pwfh, *pwfl, *paf, *pvtf, *paof, *pwof;
    cudaGetSymbolAddress((void**)&pqkv, g_qkv);
    cudaGetSymbolAddress((void**)&pbm, g_bm);   cudaGetSymbolAddress((void**)&pattn, g_attn);
    cudaGetSymbolAddress((void**)&pqh, g_qh);   cudaGetSymbolAddress((void**)&pql, g_ql);
    cudaGetSymbolAddress((void**)&pkh, g_kh);   cudaGetSymbolAddress((void**)&pkl, g_kl);
    cudaGetSymbolAddress((void**)&pxf, g_xf);
    cudaGetSymbolAddress((void**)&pwfh, g_wfh); cudaGetSymbolAddress((void**)&pwfl, g_wfl);
    cudaGetSymbolAddress((void**)&paf, g_af);   cudaGetSymbolAddress((void**)&pvtf, g_vtf);
    cudaGetSymbolAddress((void**)&paof, g_aof); cudaGetSymbolAddress((void**)&pwof, g_wof);

    const long long OUT_N = 8388608LL, ATT_N = 134217728LL;
    float* outPtr = out;
    float* attnPtr;
    int writeAttn = 1;
    long long osz = (long long)out_size;
    if (osz >= OUT_N + ATT_N) { attnPtr = out + OUT_N; }
    else if (osz == ATT_N)    { attnPtr = out; outPtr = pqkv; }
    else                      { attnPtr = pattn; writeAttn = 0; }

    const long long SH = (long long)SQ * HID;
    const long long SS = (long long)SQ * SQ;
    const long long WW = (long long)HID * HID;
    const long long QKVS = (long long)MR * HID;
    const int SMEM  = 3 * 40960;
    const int SMEM2 = 3 * 30720;
    const int SMEM1 = 3 * 20480;
    cudaFuncSetAttribute(mma_gemm,  cudaFuncAttributeMaxDynamicSharedMemorySize, SMEM);
    cudaFuncSetAttribute(mma_gemm2, cudaFuncAttributeMaxDynamicSharedMemorySize, SMEM2);
    cudaFuncSetAttribute(mma_gemm1, cudaFuncAttributeMaxDynamicSharedMemorySize, SMEM1);

    splitf1_kernel<<<8192, 256>>>(x, pxf, 2097152);
    splitf2_kernel<<<4096, 256>>>(Wq, pwfh,        pwfl,        1048576);
    splitf2_kernel<<<4096, 256>>>(Wk, pwfh + WW,   pwfl + WW,   1048576);
    splitf2_kernel<<<4096, 256>>>(Wv, pwfh + 2*WW, pwfl + 2*WW, 1048576);
    splitf1_kernel<<<4096, 256>>>(Wo, pwof, 1048576);

    // merged QKV projection : 2-pass fp16 (x single, W hi/lo)
    dim3 gQKV(16, 32, 3);
    mma_gemm2<<<gQKV, 256, SMEM2>>>(pxf, pwfh, pwfl, pqkv, 2048, 2048, 2048, 2048,
                                    0, 0, WW, 0, QKVS, 0, 1, 1.0f, 0);

    bmean_kernel<<<SQ, 256>>>(bias, pbm);

    float* pq = pqkv;
    float* pk = pqkv + QKVS;
    float* pv = pqkv + 2 * QKVS;
    rope_split_kernel<<<16384, 256>>>(pq, pk, pbm, pqh, pql, pkh, pkl);
    vsplit_kernel<<<dim3(64, 4, 32), dim3(32, 8)>>>(pv, pvtf);

    // scores = q.k^T / sqrt(128) : 3-pass bf16 (accurate attn path), causal tile-skip
    dim3 gScore(16, 16, 32);
    mma_gemm<<<gScore, 256, SMEM>>>(pqh, pql, pkh, pkl, attnPtr, 128, 2048, 2048, 2048,
                                    SH, 128, SH, 128,
                                    16 * SS, SS, 16, 0.08838834764831845f, 1);

    softmax_kernel<<<dim3(SQ, 32), 256>>>(attnPtr, bias, paf, writeAttn);

    // attn @ v : 1-pass fp16, HALF output directly into ao fp16 (no split pass)
    dim3 gAV(1, 16, 32);
    mma_gemm1<<<gAV, 256, SMEM1>>>(paf, pvtf, nullptr, paof, 2048, 2048, 2048, 2048,
                                   16 * SS, SS, SH, (long long)128 * SQ,
                                   SH, 128, 16, 1.0f, 6);

    // output = attn_out @ Wo^T : 1-pass fp16, float output
    dim3 gProj(16, 32, 1);
    mma_gemm1<<<gProj, 256, SMEM1>>>(paof, pwof, outPtr, nullptr, 2048, 2048, 2048, 2048,
                                     0, 0, 0, 0, 0, 0, 1, 1.0f, 0);
}

// round 17
// speedup vs baseline: 1.7429x; 1.2014x over previous
#include <cuda_runtime.h>
#include <cuda_bf16.h>
#include <cuda_fp16.h>
#include <math.h>
#include <stdint.h>

#define SQ   2048
#define HID  2048
#define MR   4096

typedef __nv_bfloat16  bf16;
typedef __nv_bfloat162 bf162;

// ----------------------------- static scratch ------------------------------
__device__ float g_qkv[3u * MR * HID];
__device__ float g_bm [SQ];
__device__ float g_attn[134217728];

__device__ bf16 g_qh [MR * HID],  g_ql [MR * HID];
__device__ bf16 g_kh [MR * HID],  g_kl [MR * HID];

__device__ __half g_xf  [MR * HID];                    // x fp16 (single)
__device__ __half g_wf  [3u * HID * HID];              // Wq,Wk,Wv fp16 (single)
__device__ __half g_af  [134217728];                   // attn fp16 (single)
__device__ __half g_vtf [MR * HID];                    // vT fp16 (single)
__device__ __half g_aof [MR * HID];                    // ao fp16 (single)
__device__ __half g_wof [HID * HID];                   // Wo fp16 (single)

// ----------------------------- helpers -------------------------------------
__device__ __forceinline__ uint32_t smem_u32(const void* p) {
    uint32_t a;
    asm("{ .reg .u64 t; cvta.to.shared.u64 t, %1; cvt.u32.u64 %0, t; }" : "=r"(a) : "l"(p));
    return a;
}
__device__ __forceinline__ void cp16(uint32_t dst, const void* src) {
    asm volatile("cp.async.cg.shared.global [%0], [%1], 16;" :: "r"(dst), "l"(src));
}
#define CP_COMMIT() asm volatile("cp.async.commit_group;" ::: "memory")
#define CP_WAIT(n)  asm volatile("cp.async.wait_group %0;" :: "n"(n) : "memory")

#define LDSM4(r0, r1, r2, r3, addr) \
    asm volatile("ldmatrix.sync.aligned.m8n8.x4.shared.b16 {%0,%1,%2,%3}, [%4];" \
        : "=r"(r0), "=r"(r1), "=r"(r2), "=r"(r3) : "r"(addr))

__device__ __forceinline__ void mma_bf16(float* c,
    uint32_t a0, uint32_t a1, uint32_t a2, uint32_t a3, uint32_t b0, uint32_t b1)
{
    asm volatile(
        "mma.sync.aligned.m16n8k16.row.col.f32.bf16.bf16.f32 "
        "{%0,%1,%2,%3}, {%4,%5,%6,%7}, {%8,%9}, {%0,%1,%2,%3};"
        : "+f"(c[0]), "+f"(c[1]), "+f"(c[2]), "+f"(c[3])
        : "r"(a0), "r"(a1), "r"(a2), "r"(a3), "r"(b0), "r"(b1));
}
__device__ __forceinline__ void mma_f16(float* c,
    uint32_t a0, uint32_t a1, uint32_t a2, uint32_t a3, uint32_t b0, uint32_t b1)
{
    asm volatile(
        "mma.sync.aligned.m16n8k16.row.col.f32.f16.f16.f32 "
        "{%0,%1,%2,%3}, {%4,%5,%6,%7}, {%8,%9}, {%0,%1,%2,%3};"
        : "+f"(c[0]), "+f"(c[1]), "+f"(c[2]), "+f"(c[3])
        : "r"(a0), "r"(a1), "r"(a2), "r"(a3), "r"(b0), "r"(b1));
}

// =================================================================================
// 3-pass split-bf16 NT GEMM (exact path): scores only.
// =================================================================================
#define STG_BYTES 40960u
#define ARR_BYTES 10240u

__device__ __forceinline__ void load_stage32(
    uint32_t sbase, int slot, int k0,
    const bf16* __restrict__ Ah, const bf16* __restrict__ Al,
    const bf16* __restrict__ Bh, const bf16* __restrict__ Bl,
    int lda, int ldb, int rowBase, int colBase, int tid)
{
    uint32_t base = sbase + (uint32_t)slot * STG_BYTES;
    int r  = tid >> 1;
    int c0 = (tid & 1) << 1;
#pragma unroll
    for (int i = 0; i < 2; i++) {
        int c = c0 + i;
        uint32_t off = (uint32_t)(r * 40 + c * 8) * 2;
        const size_t ga = (size_t)(rowBase + r) * lda + k0 + c * 8;
        const size_t gb = (size_t)(colBase + r) * ldb + k0 + c * 8;
        cp16(base +                off, Ah + ga);
        cp16(base + ARR_BYTES    + off, Al + ga);
        cp16(base + 2u*ARR_BYTES + off, Bh + gb);
        cp16(base + 3u*ARR_BYTES + off, Bl + gb);
    }
    CP_COMMIT();
}

__global__ void __launch_bounds__(256, 1)
mma_gemm(const bf16* __restrict__ Ahi, const bf16* __restrict__ Alo,
         const bf16* __restrict__ Bhi, const bf16* __restrict__ Blo,
         float* __restrict__ C,
         int K, int lda, int ldb, int ldc,
         long long aSb, long long aSh, long long bSb, long long bSh,
         long long cSb, long long cSh, int nInner, float scale, int mode)
{
    extern __shared__ char smem[];
    const int z  = blockIdx.z;
    const int bb = z / nInner, hh = z - bb * nInner;
    const bf16* Ah = Ahi + bb * aSb + hh * aSh;
    const bf16* Al = Alo + bb * aSb + hh * aSh;
    const bf16* Bh = Bhi + bb * bSb + hh * bSh;
    const bf16* Bl = Blo + bb * bSb + hh * bSh;
    float* Cz = C + bb * cSb + hh * cSh;

    const int yIdx = (mode & 4) ? (gridDim.y - 1 - blockIdx.y) : blockIdx.y;
    const int rowBase = yIdx * 128;
    const int colBase = blockIdx.x * 128;
    if ((mode & 1) && colBase > rowBase + 127) return;
    int Keff = K;
    if (mode & 2) { int kl = rowBase + 128; Keff = kl < K ? kl : K; }
    const int nst = Keff >> 5;

    const uint32_t sb = smem_u32(smem);
    const int tid = threadIdx.x, lane = tid & 31, wid = tid >> 5;
    const int warpM = (wid & 1) << 6;
    const int warpN = (wid >> 1) << 5;

    const uint32_t offA = (uint32_t)((warpM + (lane & 15)) * 40
                                     + ((lane >> 4) << 3)) * 2;
    const uint32_t offB = (uint32_t)((warpN + (lane & 7) + ((lane >> 4) << 3)) * 40
                                     + (((lane >> 3) & 1) << 3)) * 2;

    float acc[4][4][4];
#pragma unroll
    for (int i = 0; i < 4; i++)
#pragma unroll
        for (int j = 0; j < 4; j++)
#pragma unroll
            for (int t = 0; t < 4; t++) acc[i][j][t] = 0.f;

    load_stage32(sb, 0, 0, Ah, Al, Bh, Bl, lda, ldb, rowBase, colBase, tid);
    if (nst > 1)
        load_stage32(sb, 1, 32, Ah, Al, Bh, Bl, lda, ldb, rowBase, colBase, tid);

    int slot = 0;
    for (int j = 0; j < nst; j++) {
        if (j + 2 < nst) {
            int ns = slot + 2; if (ns >= 3) ns -= 3;
            load_stage32(sb, ns, (j + 2) * 32, Ah, Al, Bh, Bl,
                         lda, ldb, rowBase, colBase, tid);
            CP_WAIT(2);
        } else if (j + 1 < nst) {
            CP_WAIT(1);
        } else {
            CP_WAIT(0);
        }
        __syncthreads();

        const uint32_t base = sb + (uint32_t)slot * STG_BYTES;
#pragma unroll
        for (int ks = 0; ks < 32; ks += 16) {
            uint32_t ah[4][4], al[4][4], bh[2][4], bl[2][4];
#pragma unroll
            for (int t = 0; t < 4; t++) {
                uint32_t ad = base + offA + (uint32_t)((t * 640 + ks) * 2);
                LDSM4(ah[t][0], ah[t][1], ah[t][2], ah[t][3], ad);
                LDSM4(al[t][0], al[t][1], al[t][2], al[t][3], ad + ARR_BYTES);
            }
#pragma unroll
            for (int g = 0; g < 2; g++) {
                uint32_t bd = base + 2u*ARR_BYTES + offB + (uint32_t)((g * 640 + ks) * 2);
                LDSM4(bh[g][0], bh[g][1], bh[g][2], bh[g][3], bd);
                LDSM4(bl[g][0], bl[g][1], bl[g][2], bl[g][3], bd + ARR_BYTES);
            }
#pragma unroll
            for (int mt = 0; mt < 4; mt++) {
#pragma unroll
                for (int g = 0; g < 2; g++) {
                    mma_bf16(acc[mt][2*g],   ah[mt][0], ah[mt][1], ah[mt][2], ah[mt][3], bh[g][0], bh[g][1]);
                    mma_bf16(acc[mt][2*g+1], ah[mt][0], ah[mt][1], ah[mt][2], ah[mt][3], bh[g][2], bh[g][3]);
                    mma_bf16(acc[mt][2*g],   ah[mt][0], ah[mt][1], ah[mt][2], ah[mt][3], bl[g][0], bl[g][1]);
                    mma_bf16(acc[mt][2*g+1], ah[mt][0], ah[mt][1], ah[mt][2], ah[mt][3], bl[g][2], bl[g][3]);
                    mma_bf16(acc[mt][2*g],   al[mt][0], al[mt][1], al[mt][2], al[mt][3], bh[g][0], bh[g][1]);
                    mma_bf16(acc[mt][2*g+1], al[mt][0], al[mt][1], al[mt][2], al[mt][3], bh[g][2], bh[g][3]);
                }
            }
        }
        __syncthreads();
        if (++slot >= 3) slot = 0;
    }

    const int row0 = rowBase + warpM + (lane >> 2);
    const int col0 = colBase + warpN + (lane & 3) * 2;
#pragma unroll
    for (int mt = 0; mt < 4; mt++) {
#pragma unroll
        for (int nt = 0; nt < 4; nt++) {
            float2 v0 = make_float2(acc[mt][nt][0] * scale, acc[mt][nt][1] * scale);
            float2 v1 = make_float2(acc[mt][nt][2] * scale, acc[mt][nt][3] * scale);
            size_t r0 = (size_t)(row0 + mt * 16) * ldc + col0 + nt * 8;
            *reinterpret_cast<float2*>(Cz + r0)                   = v0;
            *reinterpret_cast<float2*>(Cz + r0 + 8 * (size_t)ldc) = v1;
        }
    }
}

// =================================================================================
// 1-pass fp16 NT GEMM: C = scale * Af * Bf^T. Float OR half output.
// Used for QKV (float out), attn@v (half out), out-proj (float out).
// =================================================================================
#define ARR2 10240u
#define STG1 20480u

__device__ __forceinline__ void load_stage32g(
    uint32_t sbase, int slot, int k0,
    const __half* __restrict__ Af, const __half* __restrict__ Bf,
    int lda, int ldb, int rowBase, int colBase, int tid)
{
    uint32_t base = sbase + (uint32_t)slot * STG1;
    int r  = tid >> 1;
    int c0 = (tid & 1) << 1;
#pragma unroll
    for (int i = 0; i < 2; i++) {
        int c = c0 + i;
        uint32_t off = (uint32_t)(r * 40 + c * 8) * 2;
        cp16(base +        off, Af + (size_t)(rowBase + r) * lda + k0 + c * 8);
        cp16(base + ARR2 + off, Bf + (size_t)(colBase + r) * ldb + k0 + c * 8);
    }
    CP_COMMIT();
}

__global__ void __launch_bounds__(256, 1)
mma_gemm1(const __half* __restrict__ Afi, const __half* __restrict__ Bfi,
          float* __restrict__ Cf, __half* __restrict__ Ch,
          int K, int lda, int ldb, int ldc,
          long long aSb, long long aSh, long long bSb, long long bSh,
          long long cSb, long long cSh, int nInner, float scale, int mode)
{
    extern __shared__ char smem[];
    const int z  = blockIdx.z;
    const int bb = z / nInner, hh = z - bb * nInner;
    const __half* Af = Afi + bb * aSb + hh * aSh;
    const __half* Bf = Bfi + bb * bSb + hh * bSh;

    const int yIdx = (mode & 4) ? (gridDim.y - 1 - blockIdx.y) : blockIdx.y;
    const int rowBase = yIdx * 128;
    const int colBase = blockIdx.x * 128;
    if ((mode & 1) && colBase > rowBase + 127) return;
    int Keff = K;
    if (mode & 2) { int kl = rowBase + 128; Keff = kl < K ? kl : K; }
    const int nst = Keff >> 5;

    const uint32_t sb = smem_u32(smem);
    const int tid = threadIdx.x, lane = tid & 31, wid = tid >> 5;
    const int warpM = (wid & 1) << 6;
    const int warpN = (wid >> 1) << 5;

    const uint32_t offA = (uint32_t)((warpM + (lane & 15)) * 40
                                     + ((lane >> 4) << 3)) * 2;
    const uint32_t offB = (uint32_t)((warpN + (lane & 7) + ((lane >> 4) << 3)) * 40
                                     + (((lane >> 3) & 1) << 3)) * 2;

    float acc[4][4][4];
#pragma unroll
    for (int i = 0; i < 4; i++)
#pragma unroll
        for (int j = 0; j < 4; j++)
#pragma unroll
            for (int t = 0; t < 4; t++) acc[i][j][t] = 0.f;

    load_stage32g(sb, 0, 0, Af, Bf, lda, ldb, rowBase, colBase, tid);
    if (nst > 1)
        load_stage32g(sb, 1, 32, Af, Bf, lda, ldb, rowBase, colBase, tid);

    int slot = 0;
    for (int j = 0; j < nst; j++) {
        if (j + 2 < nst) {
            int ns = slot + 2; if (ns >= 3) ns -= 3;
            load_stage32g(sb, ns, (j + 2) * 32, Af, Bf,
                          lda, ldb, rowBase, colBase, tid);
            CP_WAIT(2);
        } else if (j + 1 < nst) {
            CP_WAIT(1);
        } else {
            CP_WAIT(0);
        }
        __syncthreads();

        const uint32_t base = sb + (uint32_t)slot * STG1;
#pragma unroll
        for (int ks = 0; ks < 32; ks += 16) {
            uint32_t af[4][4], bf[2][4];
#pragma unroll
            for (int t = 0; t < 4; t++) {
                uint32_t ad = base + offA + (uint32_t)((t * 640 + ks) * 2);
                LDSM4(af[t][0], af[t][1], af[t][2], af[t][3], ad);
            }
#pragma unroll
            for (int g = 0; g < 2; g++) {
                uint32_t bd = base + ARR2 + offB + (uint32_t)((g * 640 + ks) * 2);
                LDSM4(bf[g][0], bf[g][1], bf[g][2], bf[g][3], bd);
            }
#pragma unroll
            for (int mt = 0; mt < 4; mt++) {
#pragma unroll
                for (int g = 0; g < 2; g++) {
                    mma_f16(acc[mt][2*g],   af[mt][0], af[mt][1], af[mt][2], af[mt][3], bf[g][0], bf[g][1]);
                    mma_f16(acc[mt][2*g+1], af[mt][0], af[mt][1], af[mt][2], af[mt][3], bf[g][2], bf[g][3]);
                }
            }
        }
        __syncthreads();
        if (++slot >= 3) slot = 0;
    }

    const int row0 = rowBase + warpM + (lane >> 2);
    const int col0 = colBase + warpN + (lane & 3) * 2;
    if (Ch) {
        __half* Cz = Ch + bb * cSb + hh * cSh;
#pragma unroll
        for (int mt = 0; mt < 4; mt++) {
#pragma unroll
            for (int nt = 0; nt < 4; nt++) {
                size_t r0 = (size_t)(row0 + mt * 16) * ldc + col0 + nt * 8;
                *reinterpret_cast<__half2*>(Cz + r0) =
                    __halves2half2(__float2half_rn(acc[mt][nt][0] * scale),
                                   __float2half_rn(acc[mt][nt][1] * scale));
                *reinterpret_cast<__half2*>(Cz + r0 + 8 * (size_t)ldc) =
                    __halves2half2(__float2half_rn(acc[mt][nt][2] * scale),
                                   __float2half_rn(acc[mt][nt][3] * scale));
            }
        }
    } else {
        float* Cz = Cf + bb * cSb + hh * cSh;
#pragma unroll
        for (int mt = 0; mt < 4; mt++) {
#pragma unroll
            for (int nt = 0; nt < 4; nt++) {
                float2 v0 = make_float2(acc[mt][nt][0] * scale, acc[mt][nt][1] * scale);
                float2 v1 = make_float2(acc[mt][nt][2] * scale, acc[mt][nt][3] * scale);
                size_t r0 = (size_t)(row0 + mt * 16) * ldc + col0 + nt * 8;
                *reinterpret_cast<float2*>(Cz + r0)                   = v0;
                *reinterpret_cast<float2*>(Cz + r0 + 8 * (size_t)ldc) = v1;
            }
        }
    }
}

// =================================================================================
// Elementwise kernels
// =================================================================================
__device__ __forceinline__ void sp(float v, bf16& h, bf16& l) {
    h = __float2bfloat16_rn(v);
    l = __float2bfloat16_rn(v - __bfloat162float(h));
}

__global__ void splitf1_kernel(const float* __restrict__ in,
                               __half* __restrict__ f, int n4)
{
    int i = blockIdx.x * 256 + threadIdx.x;
    if (i >= n4) return;
    float4 v = reinterpret_cast<const float4*>(in)[i];
    reinterpret_cast<__half2*>(f)[i * 2]     = __halves2half2(__float2half_rn(v.x), __float2half_rn(v.y));
    reinterpret_cast<__half2*>(f)[i * 2 + 1] = __halves2half2(__float2half_rn(v.z), __float2half_rn(v.w));
}

__global__ void bmean_kernel(const float* __restrict__ bias, float* __restrict__ bm)
{
    __shared__ float red[256];
    int r = blockIdx.x;
    const float* row = bias + (size_t)r * SQ;
    float s = 0.f;
    for (int i = threadIdx.x; i < SQ; i += 256) s += row[i];
    red[threadIdx.x] = s; __syncthreads();
    for (int o = 128; o; o >>= 1) {
        if (threadIdx.x < o) red[threadIdx.x] += red[threadIdx.x + o];
        __syncthreads();
    }
    if (threadIdx.x == 0) bm[r] = red[0] * (0.1f / 2048.0f);
}

__global__ void rope_split_kernel(const float* __restrict__ q, const float* __restrict__ k,
                                  const float* __restrict__ bm,
                                  bf16* __restrict__ qh, bf16* __restrict__ ql,
                                  bf16* __restrict__ kh, bf16* __restrict__ kl)
{
    __shared__ float sinvf[64];
    if (threadIdx.x < 64)
        sinvf[threadIdx.x] =
            (float)exp(-((double)(2 * threadIdx.x) / 128.0) * log(10000.0));
    __syncthreads();

    int idx = blockIdx.x * 256 + threadIdx.x;
    int d2 = idx & 63;
    int h  = (idx >> 6) & 15;
    int m  = idx >> 10;
    int s  = m & (SQ - 1);

    float sn, cs;
    sincosf((float)s * sinvf[d2], &sn, &cs);
    float b = bm[s];

    size_t off = (size_t)m * HID + (size_t)h * 128 + d2;
    float q0 = q[off], q1 = q[off + 64];
    float k0 = k[off], k1 = k[off + 64];
    float qa = q0 * cs - q1 * sn + b;
    float qb = q1 * cs + q0 * sn + b;
    float ka = k0 * cs - k1 * sn + b;
    float kb = k1 * cs + k0 * sn + b;
    bf16 h_, l_;
    sp(qa, h_, l_); qh[off]      = h_; ql[off]      = l_;
    sp(qb, h_, l_); qh[off + 64] = h_; ql[off + 64] = l_;
    sp(ka, h_, l_); kh[off]      = h_; kl[off]      = l_;
    sp(kb, h_, l_); kh[off + 64] = h_; kl[off + 64] = l_;
}

// v fp32 -> vT fp16 single [(b*16+h)*128+d][s]
__global__ void vsplit_kernel(const float* __restrict__ v, __half* __restrict__ vtf)
{
    __shared__ float t[32][33];
    int z = blockIdx.z, b = z >> 4, h = z & 15;
    int s0 = blockIdx.x * 32, d0 = blockIdx.y * 32;
    int tx = threadIdx.x, ty = threadIdx.y;
#pragma unroll
    for (int i = 0; i < 4; i++) {
        int sl = ty * 4 + i;
        t[sl][tx] = v[(size_t)(b * SQ + s0 + sl) * HID + h * 128 + d0 + tx];
    }
    __syncthreads();
#pragma unroll
    for (int i = 0; i < 4; i++) {
        int dl = ty * 4 + i;
        size_t o = ((size_t)z * 128 + d0 + dl) * SQ + s0 + tx;
        vtf[o] = __float2half_rn(t[tx][dl]);
    }
}

// causal softmax with bias; writes fp16 single attn + fp32 (if output).
__global__ void softmax_kernel(float* __restrict__ attn, const float* __restrict__ bias,
                               __half* __restrict__ af, int writeAttn)
{
    __shared__ float buf[2048];
    __shared__ float red[256];
    int qrow = blockIdx.x;
    long long base = (long long)blockIdx.y * SQ * SQ + (long long)qrow * SQ;
    float* row = attn + base;
    const float* brow = bias + (size_t)qrow * SQ;
    int L  = qrow + 1;
    int L4 = L & ~3;
    int tileEnd = ((qrow >> 7) + 1) << 7;
    int tid = threadIdx.x;

    float mx = -3.402823466e38f;
    for (int i = tid * 4; i < L4; i += 1024) {
        float4 r = *reinterpret_cast<const float4*>(row + i);
        float4 bb = *reinterpret_cast<const float4*>(brow + i);
        r.x += bb.x; r.y += bb.y; r.z += bb.z; r.w += bb.w;
        *reinterpret_cast<float4*>(buf + i) = r;
        mx = fmaxf(mx, fmaxf(fmaxf(r.x, r.y), fmaxf(r.z, r.w)));
    }
    for (int i = L4 + tid; i < L; i += 256) {
        float vv = row[i] + brow[i];
        buf[i] = vv;
        mx = fmaxf(mx, vv);
    }
    red[tid] = mx; __syncthreads();
    for (int o = 128; o; o >>= 1) {
        if (tid < o) red[tid] = fmaxf(red[tid], red[tid + o]);
        __syncthreads();
    }
    mx = red[0]; __syncthreads();

    float sum = 0.f;
    for (int i = tid; i < L; i += 256) {
        float e = __expf(buf[i] - mx);
        buf[i] = e;
        sum += e;
    }
    red[tid] = sum; __syncthreads();
    for (int o = 128; o; o >>= 1) {
        if (tid < o) red[tid] += red[tid + o];
        __syncthreads();
    }
    float inv = 1.0f / red[0];
    __syncthreads();

    for (int i = tid * 4; i < L4; i += 1024) {
        float a0 = buf[i]     * inv;
        float a1 = buf[i + 1] * inv;
        float a2 = buf[i + 2] * inv;
        float a3 = buf[i + 3] * inv;
        *reinterpret_cast<__half2*>(af + base + i)     =
            __halves2half2(__float2half_rn(a0), __float2half_rn(a1));
        *reinterpret_cast<__half2*>(af + base + i + 2) =
            __halves2half2(__float2half_rn(a2), __float2half_rn(a3));
        if (writeAttn)
            *reinterpret_cast<float4*>(row + i) = make_float4(a0, a1, a2, a3);
    }
    for (int i = L4 + tid; i < L; i += 256) {
        float a = buf[i] * inv;
        af[base + i] = __float2half_rn(a);
        if (writeAttn) row[i] = a;
    }
    __half z16 = __float2half_rn(0.f);
    for (int i = L + tid; i < tileEnd; i += 256) af[base + i] = z16;
    if (writeAttn)
        for (int i = L + tid; i < SQ; i += 256) row[i] = 0.f;
}

// =================================================================================
// Host launcher
// =================================================================================
extern "C" void kernel_launch(void* const* d_in, const int* in_sizes, int n_in,
                              void* d_out, int out_size)
{
    const float* x    = (const float*)d_in[0];
    const float* Wq   = (const float*)d_in[1];
    const float* Wk   = (const float*)d_in[2];
    const float* Wv   = (const float*)d_in[3];
    const float* Wo   = (const float*)d_in[4];
    const float* bias = (const float*)d_in[5];
    float* out = (float*)d_out;

    float *pqkv, *pbm, *pattn;
    bf16 *pqh, *pql, *pkh, *pkl;
    __half *pxf, *pwf, *paf, *pvtf, *paof, *pwof;
    cudaGetSymbolAddress((void**)&pqkv, g_qkv);
    cudaGetSymbolAddress((void**)&pbm, g_bm);   cudaGetSymbolAddress((void**)&pattn, g_attn);
    cudaGetSymbolAddress((void**)&pqh, g_qh);   cudaGetSymbolAddress((void**)&pql, g_ql);
    cudaGetSymbolAddress((void**)&pkh, g_kh);   cudaGetSymbolAddress((void**)&pkl, g_kl);
    cudaGetSymbolAddress((void**)&pxf, g_xf);   cudaGetSymbolAddress((void**)&pwf, g_wf);
    cudaGetSymbolAddress((void**)&paf, g_af);   cudaGetSymbolAddress((void**)&pvtf, g_vtf);
    cudaGetSymbolAddress((void**)&paof, g_aof); cudaGetSymbolAddress((void**)&pwof, g_wof);

    const long long OUT_N = 8388608LL, ATT_N = 134217728LL;
    float* outPtr = out;
    float* attnPtr;
    int writeAttn = 1;
    long long osz = (long long)out_size;
    if (osz >= OUT_N + ATT_N) { attnPtr = out + OUT_N; }
    else if (osz == ATT_N)    { attnPtr = out; outPtr = pqkv; }
    else                      { attnPtr = pattn; writeAttn = 0; }

    const long long SH = (long long)SQ * HID;
    const long long SS = (long long)SQ * SQ;
    const long long WW = (long long)HID * HID;
    const long long QKVS = (long long)MR * HID;
    const int SMEM  = 3 * 40960;
    const int SMEM1 = 3 * 20480;
    cudaFuncSetAttribute(mma_gemm,  cudaFuncAttributeMaxDynamicSharedMemorySize, SMEM);
    cudaFuncSetAttribute(mma_gemm1, cudaFuncAttributeMaxDynamicSharedMemorySize, SMEM1);

    splitf1_kernel<<<8192, 256>>>(x, pxf, 2097152);
    splitf1_kernel<<<4096, 256>>>(Wq, pwf,          1048576);
    splitf1_kernel<<<4096, 256>>>(Wk, pwf + WW,     1048576);
    splitf1_kernel<<<4096, 256>>>(Wv, pwf + 2*WW,   1048576);
    splitf1_kernel<<<4096, 256>>>(Wo, pwof, 1048576);

    // merged QKV projection : 1-pass fp16 (x single, W single), float out
    dim3 gQKV(16, 32, 3);
    mma_gemm1<<<gQKV, 256, SMEM1>>>(pxf, pwf, pqkv, nullptr, 2048, 2048, 2048, 2048,
                                    0, 0, WW, 0, QKVS, 0, 1, 1.0f, 0);

    bmean_kernel<<<SQ, 256>>>(bias, pbm);

    float* pq = pqkv;
    float* pk = pqkv + QKVS;
    float* pv = pqkv + 2 * QKVS;
    rope_split_kernel<<<16384, 256>>>(pq, pk, pbm, pqh, pql, pkh, pkl);
    vsplit_kernel<<<dim3(64, 4, 32), dim3(32, 8)>>>(pv, pvtf);

    // scores = q.k^T / sqrt(128) : 3-pass bf16 (accurate attn path), causal tile-skip
    dim3 gScore(16, 16, 32);
    mma_gemm<<<gScore, 256, SMEM>>>(pqh, pql, pkh, pkl, attnPtr, 128, 2048, 2048, 2048,
                                    SH, 128, SH, 128,
                                    16 * SS, SS, 16, 0.08838834764831845f, 1);

    softmax_kernel<<<dim3(SQ, 32), 256>>>(attnPtr, bias, paf, writeAttn);

    // attn @ v : 1-pass fp16, half out directly into ao fp16
    dim3 gAV(1, 16, 32);
    mma_gemm1<<<gAV, 256, SMEM1>>>(paf, pvtf, nullptr, paof, 2048, 2048, 2048, 2048,
                                   16 * SS, SS, SH, (long long)128 * SQ,
                                   SH, 128, 16, 1.0f, 6);

    // output = attn_out @ Wo^T : 1-pass fp16, float out
    dim3 gProj(16, 32, 1);
    mma_gemm1<<<gProj, 256, SMEM1>>>(paof, pwof, outPtr, nullptr, 2048, 2048, 2048, 2048,
                                     0, 0, 0, 0, 0, 0, 1, 1.0f, 0);
}